// round 3
// baseline (speedup 1.0000x reference)
#include <cuda_runtime.h>
#include <cuda_bf16.h>
#include <math.h>

// Problem constants
#define B_SZ 8
#define D_MODEL 2048
#define H_N 16
#define D_H 128
#define D_V 128
#define R_DIM 64
#define W_TOT 8192
#define NB 64
#define QKV_COLS (H_N * (2 * D_H + D_V))   // 6144

// Output layout (concatenated flat float32):
// out (8,2048) | M_new (8,16,64,64) | z_new (8,16,64) | S_new (8,16,64,64)
#define OUT_OFF 0
#define M_OFF   (B_SZ * H_N * D_V)                       // 16384
#define Z_OFF   (M_OFF + B_SZ * H_N * R_DIM * R_DIM)     // 540672
#define S_OFF   (Z_OFF + B_SZ * H_N * R_DIM)             // 548864

#define LOG2_GAMMA (-0.043943347587597055f)   // log2(0.97)

// -------- scratch (device globals; no allocation allowed) --------
__device__ __align__(16) float g_h[B_SZ * D_MODEL];
__device__ __align__(16) float g_qkv[B_SZ * QKV_COLS];
__device__ __align__(16) float g_QL[B_SZ * H_N * R_DIM];
__device__ __align__(16) float g_KL[B_SZ * H_N * R_DIM];
__device__ __align__(16) float g_VL[B_SZ * H_N * R_DIM];
__device__ __align__(16) float g_attn[B_SZ * H_N * R_DIM];

// -------- helpers --------
__device__ __forceinline__ float softplusf(float x) {
    return fmaxf(x, 0.0f) + log1pf(expf(-fabsf(x)));
}
__device__ __forceinline__ float geluf(float x) {
    return 0.5f * x * (1.0f + erff(x * 0.70710678118654752440f));
}
__device__ __forceinline__ float sigmoidf(float x) {
    return 1.0f / (1.0f + expf(-x));
}

// ============================================================
// Kernel 1: LayerNorm   grid=8, block=256
// ============================================================
__global__ void k_ln(const float* __restrict__ x,
                     const float* __restrict__ g,
                     const float* __restrict__ bb) {
    int b = blockIdx.x, tid = threadIdx.x;
    __shared__ float red[256];
    const float* xr = x + b * D_MODEL;

    float s = 0.0f;
    for (int i = tid; i < D_MODEL; i += 256) s += xr[i];
    red[tid] = s; __syncthreads();
    for (int o = 128; o; o >>= 1) { if (tid < o) red[tid] += red[tid + o]; __syncthreads(); }
    float mu = red[0] * (1.0f / D_MODEL);
    __syncthreads();

    float v = 0.0f;
    for (int i = tid; i < D_MODEL; i += 256) { float d = xr[i] - mu; v += d * d; }
    red[tid] = v; __syncthreads();
    for (int o = 128; o; o >>= 1) { if (tid < o) red[tid] += red[tid + o]; __syncthreads(); }
    float inv = 1.0f / sqrtf(red[0] * (1.0f / D_MODEL) + 1e-5f);

    for (int i = tid; i < D_MODEL; i += 256)
        g_h[b * D_MODEL + i] = (xr[i] - mu) * inv * g[i] + bb[i];
}

// ============================================================
// Kernel 2: qkv = h @ W_qkv^T   grid=384 (16 cols each), block=256
// Each warp: 2 output cols x 8 batches, float4, smem-tiled h.
// ============================================================
__global__ void __launch_bounds__(256) k_qkv(const float* __restrict__ W) {
    __shared__ float4 hs[B_SZ][128];   // 8 x 512 floats = 16 KB
    int tid = threadIdx.x;
    int warp = tid >> 5, lane = tid & 31;
    int colBase = blockIdx.x * 16 + warp * 2;

    float acc[2][8];
#pragma unroll
    for (int c = 0; c < 2; c++)
#pragma unroll
        for (int b = 0; b < 8; b++) acc[c][b] = 0.0f;

    for (int tile = 0; tile < 4; ++tile) {
        int k0 = tile * 512;
        for (int i = tid; i < 1024; i += 256) {
            int b = i >> 7, kk = i & 127;
            hs[b][kk] = *(const float4*)(&g_h[b * D_MODEL + k0 + kk * 4]);
        }
        __syncthreads();
#pragma unroll
        for (int kk = 0; kk < 4; ++kk) {
            int k4 = lane + kk * 32;
            float4 wv[2];
#pragma unroll
            for (int c = 0; c < 2; c++)
                wv[c] = *(const float4*)(&W[(size_t)(colBase + c) * D_MODEL + k0 + k4 * 4]);
#pragma unroll
            for (int b = 0; b < 8; b++) {
                float4 hv = hs[b][k4];
#pragma unroll
                for (int c = 0; c < 2; c++)
                    acc[c][b] += wv[c].x * hv.x + wv[c].y * hv.y + wv[c].z * hv.z + wv[c].w * hv.w;
            }
        }
        __syncthreads();
    }
#pragma unroll
    for (int c = 0; c < 2; c++)
#pragma unroll
        for (int b = 0; b < 8; b++) {
            float v = acc[c][b];
            for (int o = 16; o; o >>= 1) v += __shfl_down_sync(0xffffffffu, v, o);
            if (lane == 0) g_qkv[b * QKV_COLS + colBase + c] = v;
        }
}

// ============================================================
// Kernel 3: latent projections Q_L/K_L/V_L   grid=128, block=192
// ============================================================
__global__ void k_proj(const float* __restrict__ Eq,
                       const float* __restrict__ Ek,
                       const float* __restrict__ Ev) {
    int bh = blockIdx.x;
    int b = bh >> 4, h = bh & 15;
    int which = threadIdx.x / 64;
    int r = threadIdx.x & 63;

    const float* vec = g_qkv + b * QKV_COLS + h * 384 + which * 128;
    const float* E = (which == 0 ? Eq : (which == 1 ? Ek : Ev)) + (size_t)h * 128 * 64 + r;
    float acc = 0.0f;
#pragma unroll 8
    for (int d = 0; d < 128; ++d) acc += vec[d] * E[d * 64];

    float* dst = (which == 0 ? g_QL : (which == 1 ? g_KL : g_VL));
    dst[bh * 64 + r] = acc;
}

// ============================================================
// Kernel 4: fused routing + top-2 + compaction + softmax attention
// grid=128 (b,h), block=256, dynamic smem 64KB (widx + logit)
// Each block redundantly computes its batch's routing (bm is L2-resident
// after first touch; 128-way SM parallelism for the DRAM pull).
// ============================================================
__global__ void __launch_bounds__(256) k_attn(
    const float* __restrict__ Kl, const float* __restrict__ Vl,
    const float* __restrict__ bm, const int* __restrict__ bids,
    const int* __restrict__ curp) {

    extern __shared__ __align__(16) char dyn[];
    int*   widx  = (int*)dyn;                 // [8192]
    float* logit = (float*)(dyn + W_TOT * 4); // [8192]

    __shared__ __align__(16) float QLall[H_N * 64];   // all heads of this batch
    __shared__ float part[64][17];
    __shared__ float sarr[64];
    __shared__ float red[256];
    __shared__ __align__(16) float accv[16][64];
    __shared__ int warpBase[9];
    __shared__ int s_i1, s_i2;
    __shared__ float s_max, s_sum;

    int bh = blockIdx.x;
    int b = bh >> 4, h0 = bh & 15;
    int tid = threadIdx.x;
    int warp = tid >> 5, lane = tid & 31;

    // load all 16 heads' Q_L for this batch (1024 floats)
    ((float4*)QLall)[tid] = ((const float4*)(g_QL + b * H_N * 64))[tid];
    __syncthreads();

    // ---- scores: 64 nodes x 16 heads, 4 (n,h) pairs per thread ----
#pragma unroll
    for (int p = 0; p < 4; ++p) {
        int idx = p * 256 + tid;
        int n = idx >> 4, h = idx & 15;
        const float4* mrow = (const float4*)&bm[(((size_t)n * B_SZ + b) * H_N + h) * 64];
        const float4* qrow = (const float4*)&QLall[h * 64];
        float d = 0.0f;
#pragma unroll
        for (int r4 = 0; r4 < 16; ++r4) {
            float4 mv = mrow[r4], qv = qrow[r4];
            d += mv.x * qv.x + mv.y * qv.y + mv.z * qv.z + mv.w * qv.w;
        }
        part[n][h] = d;
    }
    __syncthreads();
    if (tid < 64) {
        float s = 0.0f;
#pragma unroll
        for (int h = 0; h < 16; ++h) s += part[tid][h];
        // * gamma^(63-n) / (sqrt(R) * H)
        sarr[tid] = s * exp2f((float)(63 - tid) * LOG2_GAMMA) * 0.0078125f;
    }
    __syncthreads();

    // ---- top-2 (lower index wins ties, matching lax.top_k) ----
    if (tid < 32) {
        float v0 = sarr[tid], v1 = sarr[tid + 32];
        float bv; int bi;
        if (v0 >= v1) { bv = v0; bi = tid; } else { bv = v1; bi = tid + 32; }
#pragma unroll
        for (int o = 16; o; o >>= 1) {
            float ov = __shfl_down_sync(0xffffffffu, bv, o);
            int   oi = __shfl_down_sync(0xffffffffu, bi, o);
            if (ov > bv || (ov == bv && oi < bi)) { bv = ov; bi = oi; }
        }
        int i1 = __shfl_sync(0xffffffffu, bi, 0);
        float w0 = (tid == i1)      ? -INFINITY : sarr[tid];
        float w1 = (tid + 32 == i1) ? -INFINITY : sarr[tid + 32];
        float cv; int ci;
        if (w0 >= w1) { cv = w0; ci = tid; } else { cv = w1; ci = tid + 32; }
#pragma unroll
        for (int o = 16; o; o >>= 1) {
            float ov = __shfl_down_sync(0xffffffffu, cv, o);
            int   oi = __shfl_down_sync(0xffffffffu, ci, o);
            if (ov > cv || (ov == cv && oi < ci)) { cv = ov; ci = oi; }
        }
        if (tid == 0) { s_i1 = i1; s_i2 = ci; }
    }
    __syncthreads();

    // ---- deterministic compaction: warp-chunked ballot/prefix ----
    int cur = curp[0];
    int i1 = s_i1, i2 = s_i2;
    const int* br = bids + b * W_TOT;
    int wbase = warp * 1024;

    int cnt = 0;
#pragma unroll 4
    for (int j = 0; j < 32; ++j) {
        int w = wbase + j * 32 + lane;
        int id = br[w];
        unsigned bal = __ballot_sync(0xffffffffu, id == i1 || id == i2 || id == cur);
        cnt += __popc(bal);
    }
    if (lane == 0) warpBase[warp] = cnt;
    __syncthreads();
    if (tid == 0) {
        int t = 0;
#pragma unroll
        for (int k = 0; k < 8; ++k) { int c = warpBase[k]; warpBase[k] = t; t += c; }
        warpBase[8] = t;
    }
    __syncthreads();
    int nw = warpBase[8];
    {
        int off = warpBase[warp];
        unsigned lmask = (1u << lane) - 1u;
        for (int j = 0; j < 32; ++j) {
            int w = wbase + j * 32 + lane;
            int id = br[w];
            bool m = (id == i1 || id == i2 || id == cur);
            unsigned bal = __ballot_sync(0xffffffffu, m);
            if (m) widx[off + __popc(bal & lmask)] = w;
            off += __popc(bal);
        }
    }
    __syncthreads();

    // ---- logits + max over routed list (own head h0) ----
    const float4* qr = (const float4*)&QLall[h0 * 64];
    float lm = -INFINITY;
    for (int i = tid; i < nw; i += 256) {
        int w = widx[i];
        const float4* kr = (const float4*)&Kl[((size_t)bh * W_TOT + w) * 64];
        float d = 0.0f;
#pragma unroll
        for (int r4 = 0; r4 < 16; ++r4) {
            float4 kv = kr[r4], qv = qr[r4];
            d += kv.x * qv.x + kv.y * qv.y + kv.z * qv.z + kv.w * qv.w;
        }
        d *= 0.125f;   // 1/sqrt(64)
        logit[i] = d;
        lm = fmaxf(lm, d);
    }
    red[tid] = lm; __syncthreads();
    for (int o = 128; o; o >>= 1) { if (tid < o) red[tid] = fmaxf(red[tid], red[tid + o]); __syncthreads(); }
    if (tid == 0) s_max = red[0];
    __syncthreads();

    // ---- exp + sum ----
    float mx = s_max;
    float ls = 0.0f;
    for (int i = tid; i < nw; i += 256) {
        float e = expf(logit[i] - mx);
        logit[i] = e;
        ls += e;
    }
    red[tid] = ls; __syncthreads();
    for (int o = 128; o; o >>= 1) { if (tid < o) red[tid] += red[tid + o]; __syncthreads(); }
    if (tid == 0) s_sum = red[0];
    __syncthreads();

    // ---- weighted V accumulation (float4) ----
    int r4 = tid & 15, g = tid >> 4;
    float4 a4 = make_float4(0.0f, 0.0f, 0.0f, 0.0f);
    for (int i = g; i < nw; i += 16) {
        int w = widx[i];
        float pw = logit[i];
        float4 v = *(const float4*)&Vl[((size_t)bh * W_TOT + w) * 64 + r4 * 4];
        a4.x += pw * v.x; a4.y += pw * v.y; a4.z += pw * v.z; a4.w += pw * v.w;
    }
    *(float4*)&accv[g][r4 * 4] = a4;
    __syncthreads();
    if (tid < 64) {
        float a = 0.0f;
#pragma unroll
        for (int gg = 0; gg < 16; ++gg) a += accv[gg][tid];
        g_attn[bh * 64 + tid] = a / s_sum;
    }
}

// ============================================================
// Kernel 5: fused tail   grid=128 (b,h), block=256
// ============================================================
__global__ void __launch_bounds__(256) k_tail(
    const float* __restrict__ M, const float* __restrict__ z,
    const float* __restrict__ S_prev,
    const float* __restrict__ r1w, const float* __restrict__ r1b,
    const float* __restrict__ r2w, const float* __restrict__ r2b,
    const float* __restrict__ g1w, const float* __restrict__ g1b,
    const float* __restrict__ g2w, const float* __restrict__ g2b,
    const float* __restrict__ Ev, float* __restrict__ out) {

    int bh = blockIdx.x;
    int b = bh >> 4, h = bh & 15;
    int tid = threadIdx.x;

    __shared__ __align__(16) float Ms[4096];       // 16 KB
    __shared__ __align__(16) float u[256];         // [QL | KL | VL | attn]
    __shared__ __align__(16) float qf[64], zs[64], lin[64], errv[64], outlat[64];
    __shared__ __align__(16) float rh[128], gh[256], gout[192];
    __shared__ float partv[4][64];
    __shared__ float epartv[4][64];
    __shared__ float sc[8];  // 0:qz+eps 1:p_skip 2:alpha 3:eta 4:theta

    const float4* Mg4 = (const float4*)(M + (size_t)bh * 4096);
    float4* Ms4 = (float4*)Ms;
    for (int i = tid; i < 1024; i += 256) Ms4[i] = Mg4[i];
    if (tid < 64) {
        u[tid]       = g_QL[bh * 64 + tid];
        u[64 + tid]  = g_KL[bh * 64 + tid];
        u[128 + tid] = g_VL[bh * 64 + tid];
        u[192 + tid] = g_attn[bh * 64 + tid];
        zs[tid]      = z[bh * 64 + tid];
    }
    __syncthreads();

    // phase B: qf, rh, gh
    if (tid < 64) qf[tid] = softplusf(u[tid]);
    if (tid < 128) {
        const float4* wr = (const float4*)(r1w + tid * 64);
        const float4* qv = (const float4*)u;
        float a = r1b[tid];
#pragma unroll
        for (int k = 0; k < 16; ++k) {
            float4 wv = wr[k], uv = qv[k];
            a += wv.x * uv.x + wv.y * uv.y + wv.z * uv.z + wv.w * uv.w;
        }
        rh[tid] = geluf(a);
    }
    {
        const float4* wr = (const float4*)(g1w + (size_t)tid * 256);
        const float4* uv4 = (const float4*)u;
        float a = g1b[tid];
#pragma unroll
        for (int k = 0; k < 64; ++k) {
            float4 wv = wr[k], uv = uv4[k];
            a += wv.x * uv.x + wv.y * uv.y + wv.z * uv.z + wv.w * uv.w;
        }
        gh[tid] = geluf(a);
    }
    __syncthreads();

    // phase C: lin partials, err partials, gout
    {
        int s = tid & 63, g = tid >> 6;
        float a = 0.0f, e = 0.0f;
        for (int r = g; r < 64; r += 4) {
            float mrs = Ms[r * 64 + s];
            a += qf[r] * mrs;
            e += u[64 + r] * mrs;   // K_L @ M
        }
        partv[g][s] = a;
        epartv[g][s] = e;
    }
    if (tid < 192) {
        const float4* wr = (const float4*)(g2w + (size_t)tid * 256);
        const float4* gv4 = (const float4*)gh;
        float a = g2b[tid];
#pragma unroll
        for (int k = 0; k < 64; ++k) {
            float4 wv = wr[k], gv = gv4[k];
            a += wv.x * gv.x + wv.y * gv.y + wv.z * gv.z + wv.w * gv.w;
        }
        gout[tid] = a;
    }
    __syncthreads();

    // phase D: scalar reductions
    if (tid == 0) { float t = 0.0f; for (int k = 0; k < 64; ++k) t += qf[k] * zs[k]; sc[0] = t + 1e-6f; }
    if (tid == 1) { float t = r2b[0]; for (int k = 0; k < 128; ++k) t += rh[k] * r2w[k]; sc[1] = sigmoidf(t); }
    if (tid == 2) { float t = 0.0f; for (int k = 0; k < 64; ++k) t += gout[k]; sc[2] = sigmoidf(t * (1.0f / 64.0f)); }
    if (tid == 3) { float t = 0.0f; for (int k = 0; k < 64; ++k) t += gout[64 + k]; sc[3] = softplusf(t * (1.0f / 64.0f)); }
    if (tid == 4) { float t = 0.0f; for (int k = 0; k < 64; ++k) t += gout[128 + k]; sc[4] = softplusf(t * (1.0f / 64.0f)); }
    __syncthreads();

    // phase E: lin, err, out_lat, z_new
    if (tid < 64) {
        float l = (partv[0][tid] + partv[1][tid] + partv[2][tid] + partv[3][tid]) / sc[0];
        lin[tid] = l;
        errv[tid] = (epartv[0][tid] + epartv[1][tid] + epartv[2][tid] + epartv[3][tid]) - u[128 + tid];
        float ps = sc[1];
        outlat[tid] = (1.0f - ps) * u[192 + tid] + ps * l;
        float zn = (1.0f - sc[2]) * zs[tid] + softplusf(u[64 + tid]);
        out[Z_OFF + bh * 64 + tid] = zn;
    }
    __syncthreads();

    // phase F: state update (M_new, S_new) + output projection, float4
    {
        float eta = sc[3], theta = sc[4], oma = 1.0f - sc[2];
        const float4* Sg4 = (const float4*)(S_prev + (size_t)bh * 4096);
        float4* Mo4 = (float4*)(out + M_OFF + (size_t)bh * 4096);
        float4* So4 = (float4*)(out + S_OFF + (size_t)bh * 4096);
        const float4* ev4 = (const float4*)errv;
        for (int idx = tid; idx < 1024; idx += 256) {
            int r = idx >> 4, s4 = idx & 15;
            float kl = u[64 + r];
            float4 e = ev4[s4];
            float4 sg = Sg4[idx];
            float4 ms = Ms4[idx];
            float4 sn;
            sn.x = eta * sg.x - theta * (kl * e.x);
            sn.y = eta * sg.y - theta * (kl * e.y);
            sn.z = eta * sg.z - theta * (kl * e.z);
            sn.w = eta * sg.w - theta * (kl * e.w);
            So4[idx] = sn;
            float4 mn;
            mn.x = oma * ms.x + sn.x;
            mn.y = oma * ms.y + sn.y;
            mn.z = oma * ms.z + sn.z;
            mn.w = oma * ms.w + sn.w;
            Mo4[idx] = mn;
        }
    }
    if (tid < 128) {
        const float4* er = (const float4*)(Ev + ((size_t)h * 128 + tid) * 64);
        const float4* ov = (const float4*)outlat;
        float a = 0.0f;
#pragma unroll
        for (int k = 0; k < 16; ++k) {
            float4 e = er[k], o = ov[k];
            a += e.x * o.x + e.y * o.y + e.z * o.z + e.w * o.w;
        }
        out[OUT_OFF + b * (H_N * D_V) + h * 128 + tid] = a;
    }
}

// ============================================================
extern "C" void kernel_launch(void* const* d_in, const int* in_sizes, int n_in,
                              void* d_out, int out_size) {
    const float* x     = (const float*)d_in[0];
    const float* ln_g  = (const float*)d_in[1];
    const float* ln_b  = (const float*)d_in[2];
    const float* W_qkv = (const float*)d_in[3];
    const float* E_q   = (const float*)d_in[4];
    const float* E_k   = (const float*)d_in[5];
    const float* E_v   = (const float*)d_in[6];
    const float* K_lat = (const float*)d_in[7];
    const float* V_lat = (const float*)d_in[8];
    const float* bm    = (const float*)d_in[9];
    const float* M     = (const float*)d_in[10];
    const float* z     = (const float*)d_in[11];
    const float* S_prev= (const float*)d_in[12];
    const float* r1w   = (const float*)d_in[13];
    const float* r1b   = (const float*)d_in[14];
    const float* r2w   = (const float*)d_in[15];
    const float* r2b   = (const float*)d_in[16];
    const float* g1w   = (const float*)d_in[17];
    const float* g1b   = (const float*)d_in[18];
    const float* g2w   = (const float*)d_in[19];
    const float* g2b   = (const float*)d_in[20];
    const int*   bids  = (const int*)d_in[21];
    const int*   cur   = (const int*)d_in[22];
    float* out = (float*)d_out;

    static bool attr_done = false;
    if (!attr_done) {
        cudaFuncSetAttribute(k_attn, cudaFuncAttributeMaxDynamicSharedMemorySize,
                             W_TOT * 8);
        attr_done = true;
    }

    k_ln<<<B_SZ, 256>>>(x, ln_g, ln_b);
    k_qkv<<<QKV_COLS / 16, 256>>>(W_qkv);
    k_proj<<<B_SZ * H_N, 192>>>(E_q, E_k, E_v);
    k_attn<<<B_SZ * H_N, 256, W_TOT * 8>>>(K_lat, V_lat, bm, bids, cur);
    k_tail<<<B_SZ * H_N, 256>>>(M, z, S_prev, r1w, r1b, r2w, r2b,
                                g1w, g1b, g2w, g2b, E_v, out);
}

// round 4
// speedup vs baseline: 1.6463x; 1.6463x over previous
#include <cuda_runtime.h>
#include <cuda_bf16.h>
#include <math.h>

// Problem constants
#define B_SZ 8
#define D_MODEL 2048
#define H_N 16
#define D_H 128
#define D_V 128
#define R_DIM 64
#define W_TOT 8192
#define NB 64
#define QKV_COLS (H_N * (2 * D_H + D_V))   // 6144

// Output layout (concatenated flat float32):
// out (8,2048) | M_new (8,16,64,64) | z_new (8,16,64) | S_new (8,16,64,64)
#define OUT_OFF 0
#define M_OFF   (B_SZ * H_N * D_V)                       // 16384
#define Z_OFF   (M_OFF + B_SZ * H_N * R_DIM * R_DIM)     // 540672
#define S_OFF   (Z_OFF + B_SZ * H_N * R_DIM)             // 548864

#define LOG2_GAMMA (-0.043943347587597055f)   // log2(0.97)

// -------- scratch (device globals; no allocation allowed) --------
__device__ __align__(16) float g_h[B_SZ * D_MODEL];
__device__ __align__(16) float g_qkv[B_SZ * QKV_COLS];
__device__ __align__(16) float g_QL[B_SZ * H_N * R_DIM];
__device__ __align__(16) float g_KL[B_SZ * H_N * R_DIM];
__device__ __align__(16) float g_VL[B_SZ * H_N * R_DIM];
__device__ __align__(16) float g_attn[B_SZ * H_N * R_DIM];
__device__ float g_score[B_SZ * NB];
__device__ int g_widx[B_SZ * W_TOT];
__device__ int g_wcnt[B_SZ];

// -------- helpers --------
__device__ __forceinline__ float softplusf(float x) {
    return fmaxf(x, 0.0f) + log1pf(expf(-fabsf(x)));
}
__device__ __forceinline__ float geluf(float x) {
    return 0.5f * x * (1.0f + erff(x * 0.70710678118654752440f));
}
__device__ __forceinline__ float sigmoidf(float x) {
    return 1.0f / (1.0f + expf(-x));
}

// ============================================================
// Kernel 1: LayerNorm   grid=8, block=256
// ============================================================
__global__ void k_ln(const float* __restrict__ x,
                     const float* __restrict__ g,
                     const float* __restrict__ bb) {
    int b = blockIdx.x, tid = threadIdx.x;
    __shared__ float red[256];
    const float* xr = x + b * D_MODEL;

    float s = 0.0f;
    for (int i = tid; i < D_MODEL; i += 256) s += xr[i];
    red[tid] = s; __syncthreads();
    for (int o = 128; o; o >>= 1) { if (tid < o) red[tid] += red[tid + o]; __syncthreads(); }
    float mu = red[0] * (1.0f / D_MODEL);
    __syncthreads();

    float v = 0.0f;
    for (int i = tid; i < D_MODEL; i += 256) { float d = xr[i] - mu; v += d * d; }
    red[tid] = v; __syncthreads();
    for (int o = 128; o; o >>= 1) { if (tid < o) red[tid] += red[tid + o]; __syncthreads(); }
    float inv = 1.0f / sqrtf(red[0] * (1.0f / D_MODEL) + 1e-5f);

    for (int i = tid; i < D_MODEL; i += 256)
        g_h[b * D_MODEL + i] = (xr[i] - mu) * inv * g[i] + bb[i];
}

// ============================================================
// Kernel 2: qkv = h @ W_qkv^T   grid=384 (16 cols each), block=256
// ============================================================
__global__ void __launch_bounds__(256) k_qkv(const float* __restrict__ W) {
    __shared__ float4 hs[B_SZ][128];   // 8 x 512 floats = 16 KB
    int tid = threadIdx.x;
    int warp = tid >> 5, lane = tid & 31;
    int colBase = blockIdx.x * 16 + warp * 2;

    float acc[2][8];
#pragma unroll
    for (int c = 0; c < 2; c++)
#pragma unroll
        for (int b = 0; b < 8; b++) acc[c][b] = 0.0f;

    for (int tile = 0; tile < 4; ++tile) {
        int k0 = tile * 512;
        for (int i = tid; i < 1024; i += 256) {
            int b = i >> 7, kk = i & 127;
            hs[b][kk] = *(const float4*)(&g_h[b * D_MODEL + k0 + kk * 4]);
        }
        __syncthreads();
#pragma unroll
        for (int kk = 0; kk < 4; ++kk) {
            int k4 = lane + kk * 32;
            float4 wv[2];
#pragma unroll
            for (int c = 0; c < 2; c++)
                wv[c] = *(const float4*)(&W[(size_t)(colBase + c) * D_MODEL + k0 + k4 * 4]);
#pragma unroll
            for (int b = 0; b < 8; b++) {
                float4 hv = hs[b][k4];
#pragma unroll
                for (int c = 0; c < 2; c++)
                    acc[c][b] += wv[c].x * hv.x + wv[c].y * hv.y + wv[c].z * hv.z + wv[c].w * hv.w;
            }
        }
        __syncthreads();
    }
#pragma unroll
    for (int c = 0; c < 2; c++)
#pragma unroll
        for (int b = 0; b < 8; b++) {
            float v = acc[c][b];
            for (int o = 16; o; o >>= 1) v += __shfl_down_sync(0xffffffffu, v, o);
            if (lane == 0) g_qkv[b * QKV_COLS + colBase + c] = v;
        }
}

// ============================================================
// Kernel 3: latent projections Q_L/K_L/V_L   grid=128, block=192
// ============================================================
__global__ void k_proj(const float* __restrict__ Eq,
                       const float* __restrict__ Ek,
                       const float* __restrict__ Ev) {
    int bh = blockIdx.x;
    int b = bh >> 4, h = bh & 15;
    int which = threadIdx.x / 64;
    int r = threadIdx.x & 63;

    const float* vec = g_qkv + b * QKV_COLS + h * 384 + which * 128;
    const float* E = (which == 0 ? Eq : (which == 1 ? Ek : Ev)) + (size_t)h * 128 * 64 + r;
    float acc = 0.0f;
#pragma unroll 8
    for (int d = 0; d < 128; ++d) acc += vec[d] * E[d * 64];

    float* dst = (which == 0 ? g_QL : (which == 1 ? g_KL : g_VL));
    dst[bh * 64 + r] = acc;
}

// ============================================================
// Kernel 4: block scores   grid=512 (n=blockIdx>>3, b=blockIdx&7), block=256
// One coalesced 4KB bm read per block; 2MB total spread over 512 blocks.
// ============================================================
__global__ void __launch_bounds__(256) k_score(const float* __restrict__ bm) {
    int n = blockIdx.x >> 3, b = blockIdx.x & 7;
    int tid = threadIdx.x;
    int h = tid >> 4, rp = tid & 15;
    __shared__ float red[256];

    float4 qv = ((const float4*)&g_QL[(b * 16 + h) * 64])[rp];
    float4 mv = ((const float4*)&bm[(((size_t)n * B_SZ + b) * H_N + h) * 64])[rp];
    float d = qv.x * mv.x + qv.y * mv.y + qv.z * mv.z + qv.w * mv.w;

    red[tid] = d; __syncthreads();
    for (int o = 128; o; o >>= 1) { if (tid < o) red[tid] += red[tid + o]; __syncthreads(); }
    if (tid == 0)
        g_score[b * NB + n] = red[0] * exp2f((float)(63 - n) * LOG2_GAMMA) * 0.0078125f;
}

// ============================================================
// Kernel 5: top-2 + deterministic compaction   grid=8, block=256
// ============================================================
__global__ void k_route2(const int* __restrict__ bids,
                         const int* __restrict__ curp) {
    int b = blockIdx.x, tid = threadIdx.x;
    int warp = tid >> 5, lane = tid & 31;
    __shared__ int s_i1, s_i2;
    __shared__ int warpBase[9];

    // ---- top-2 over g_score[b] (lower index wins ties) ----
    if (tid < 32) {
        const float* sarr = g_score + b * NB;
        float v0 = sarr[tid], v1 = sarr[tid + 32];
        float bv; int bi;
        if (v0 >= v1) { bv = v0; bi = tid; } else { bv = v1; bi = tid + 32; }
#pragma unroll
        for (int o = 16; o; o >>= 1) {
            float ov = __shfl_down_sync(0xffffffffu, bv, o);
            int   oi = __shfl_down_sync(0xffffffffu, bi, o);
            if (ov > bv || (ov == bv && oi < bi)) { bv = ov; bi = oi; }
        }
        int i1 = __shfl_sync(0xffffffffu, bi, 0);
        float w0 = (tid == i1)      ? -INFINITY : v0;
        float w1 = (tid + 32 == i1) ? -INFINITY : v1;
        float cv; int ci;
        if (w0 >= w1) { cv = w0; ci = tid; } else { cv = w1; ci = tid + 32; }
#pragma unroll
        for (int o = 16; o; o >>= 1) {
            float ov = __shfl_down_sync(0xffffffffu, cv, o);
            int   oi = __shfl_down_sync(0xffffffffu, ci, o);
            if (ov > cv || (ov == cv && oi < ci)) { cv = ov; ci = oi; }
        }
        if (tid == 0) { s_i1 = i1; s_i2 = ci; }
    }
    __syncthreads();

    int cur = curp[0];
    int i1 = s_i1, i2 = s_i2;
    const int* br = bids + b * W_TOT;
    int wbase = warp * 1024;

    int cnt = 0;
#pragma unroll 4
    for (int j = 0; j < 32; ++j) {
        int id = br[wbase + j * 32 + lane];
        unsigned bal = __ballot_sync(0xffffffffu, id == i1 || id == i2 || id == cur);
        cnt += __popc(bal);
    }
    if (lane == 0) warpBase[warp] = cnt;
    __syncthreads();
    if (tid == 0) {
        int t = 0;
#pragma unroll
        for (int k = 0; k < 8; ++k) { int c = warpBase[k]; warpBase[k] = t; t += c; }
        warpBase[8] = t;
        g_wcnt[b] = t;
    }
    __syncthreads();
    {
        int off = warpBase[warp];
        unsigned lmask = (1u << lane) - 1u;
        for (int j = 0; j < 32; ++j) {
            int w = wbase + j * 32 + lane;
            int id = br[w];
            bool m = (id == i1 || id == i2 || id == cur);
            unsigned bal = __ballot_sync(0xffffffffu, m);
            if (m) g_widx[b * W_TOT + off + __popc(bal & lmask)] = w;
            off += __popc(bal);
        }
    }
}

// ============================================================
// Kernel 6: masked softmax attention over routed list  grid=128, block=256
// ============================================================
__global__ void __launch_bounds__(256) k_attn(const float* __restrict__ Kl,
                                              const float* __restrict__ Vl) {
    int bh = blockIdx.x;
    int b = bh >> 4;
    int tid = threadIdx.x;

    __shared__ __align__(16) float QLs[64];
    __shared__ float logit[W_TOT];
    __shared__ float red[256];
    __shared__ __align__(16) float accv[16][64];
    __shared__ float s_max, s_sum;

    int nw = g_wcnt[b];
    if (tid < 64) QLs[tid] = g_QL[bh * 64 + tid];
    __syncthreads();

    const int* wl = g_widx + b * W_TOT;

    // pass 1: logits + local max
    float lm = -INFINITY;
    for (int i = tid; i < nw; i += 256) {
        int w = wl[i];
        const float4* kr = (const float4*)&Kl[((size_t)bh * W_TOT + w) * 64];
        const float4* qr = (const float4*)QLs;
        float d = 0.0f;
#pragma unroll
        for (int r4 = 0; r4 < 16; ++r4) {
            float4 kv = kr[r4], qv = qr[r4];
            d += kv.x * qv.x + kv.y * qv.y + kv.z * qv.z + kv.w * qv.w;
        }
        d *= 0.125f;   // 1/sqrt(64)
        logit[i] = d;
        lm = fmaxf(lm, d);
    }
    red[tid] = lm; __syncthreads();
    for (int o = 128; o; o >>= 1) { if (tid < o) red[tid] = fmaxf(red[tid], red[tid + o]); __syncthreads(); }
    if (tid == 0) s_max = red[0];
    __syncthreads();

    // pass 2: exp + sum
    float mx = s_max;
    float ls = 0.0f;
    for (int i = tid; i < nw; i += 256) {
        float e = expf(logit[i] - mx);
        logit[i] = e;
        ls += e;
    }
    red[tid] = ls; __syncthreads();
    for (int o = 128; o; o >>= 1) { if (tid < o) red[tid] += red[tid + o]; __syncthreads(); }
    if (tid == 0) s_sum = red[0];
    __syncthreads();

    // weighted V accumulation, float4-vectorized
    int r4 = tid & 15, g = tid >> 4;
    float4 a4 = make_float4(0.0f, 0.0f, 0.0f, 0.0f);
    for (int i = g; i < nw; i += 16) {
        int w = wl[i];
        float pw = logit[i];
        float4 v = *(const float4*)&Vl[((size_t)bh * W_TOT + w) * 64 + r4 * 4];
        a4.x += pw * v.x; a4.y += pw * v.y; a4.z += pw * v.z; a4.w += pw * v.w;
    }
    *(float4*)&accv[g][r4 * 4] = a4;
    __syncthreads();
    if (tid < 64) {
        float a = 0.0f;
#pragma unroll
        for (int gg = 0; gg < 16; ++gg) a += accv[gg][tid];
        g_attn[bh * 64 + tid] = a / s_sum;
    }
}

// ============================================================
// Kernel 7: fused tail   grid=128 (b,h), block=256
// ============================================================
__global__ void __launch_bounds__(256) k_tail(
    const float* __restrict__ M, const float* __restrict__ z,
    const float* __restrict__ S_prev,
    const float* __restrict__ r1w, const float* __restrict__ r1b,
    const float* __restrict__ r2w, const float* __restrict__ r2b,
    const float* __restrict__ g1w, const float* __restrict__ g1b,
    const float* __restrict__ g2w, const float* __restrict__ g2b,
    const float* __restrict__ Ev, float* __restrict__ out) {

    int bh = blockIdx.x;
    int b = bh >> 4, h = bh & 15;
    int tid = threadIdx.x;

    __shared__ __align__(16) float Ms[4096];       // 16 KB
    __shared__ __align__(16) float u[256];         // [QL | KL | VL | attn]
    __shared__ __align__(16) float qf[64], zs[64], lin[64], errv[64], outlat[64];
    __shared__ __align__(16) float rh[128], gh[256], gout[192];
    __shared__ float partv[4][64];
    __shared__ float epartv[4][64];
    __shared__ float sc[8];  // 0:qz+eps 1:p_skip 2:alpha 3:eta 4:theta

    const float4* Mg4 = (const float4*)(M + (size_t)bh * 4096);
    float4* Ms4 = (float4*)Ms;
    for (int i = tid; i < 1024; i += 256) Ms4[i] = Mg4[i];
    if (tid < 64) {
        u[tid]       = g_QL[bh * 64 + tid];
        u[64 + tid]  = g_KL[bh * 64 + tid];
        u[128 + tid] = g_VL[bh * 64 + tid];
        u[192 + tid] = g_attn[bh * 64 + tid];
        zs[tid]      = z[bh * 64 + tid];
    }
    __syncthreads();

    // phase B: qf, rh, gh
    if (tid < 64) qf[tid] = softplusf(u[tid]);
    if (tid < 128) {
        const float4* wr = (const float4*)(r1w + tid * 64);
        const float4* qv = (const float4*)u;
        float a = r1b[tid];
#pragma unroll
        for (int k = 0; k < 16; ++k) {
            float4 wv = wr[k], uv = qv[k];
            a += wv.x * uv.x + wv.y * uv.y + wv.z * uv.z + wv.w * uv.w;
        }
        rh[tid] = geluf(a);
    }
    {
        const float4* wr = (const float4*)(g1w + (size_t)tid * 256);
        const float4* uv4 = (const float4*)u;
        float a = g1b[tid];
#pragma unroll
        for (int k = 0; k < 64; ++k) {
            float4 wv = wr[k], uv = uv4[k];
            a += wv.x * uv.x + wv.y * uv.y + wv.z * uv.z + wv.w * uv.w;
        }
        gh[tid] = geluf(a);
    }
    __syncthreads();

    // phase C: lin partials, err partials, gout
    {
        int s = tid & 63, g = tid >> 6;
        float a = 0.0f, e = 0.0f;
        for (int r = g; r < 64; r += 4) {
            float mrs = Ms[r * 64 + s];
            a += qf[r] * mrs;
            e += u[64 + r] * mrs;   // K_L @ M
        }
        partv[g][s] = a;
        epartv[g][s] = e;
    }
    if (tid < 192) {
        const float4* wr = (const float4*)(g2w + (size_t)tid * 256);
        const float4* gv4 = (const float4*)gh;
        float a = g2b[tid];
#pragma unroll
        for (int k = 0; k < 64; ++k) {
            float4 wv = wr[k], gv = gv4[k];
            a += wv.x * gv.x + wv.y * gv.y + wv.z * gv.z + wv.w * gv.w;
        }
        gout[tid] = a;
    }
    __syncthreads();

    // phase D: scalar reductions
    if (tid == 0) { float t = 0.0f; for (int k = 0; k < 64; ++k) t += qf[k] * zs[k]; sc[0] = t + 1e-6f; }
    if (tid == 1) { float t = r2b[0]; for (int k = 0; k < 128; ++k) t += rh[k] * r2w[k]; sc[1] = sigmoidf(t); }
    if (tid == 2) { float t = 0.0f; for (int k = 0; k < 64; ++k) t += gout[k]; sc[2] = sigmoidf(t * (1.0f / 64.0f)); }
    if (tid == 3) { float t = 0.0f; for (int k = 0; k < 64; ++k) t += gout[64 + k]; sc[3] = softplusf(t * (1.0f / 64.0f)); }
    if (tid == 4) { float t = 0.0f; for (int k = 0; k < 64; ++k) t += gout[128 + k]; sc[4] = softplusf(t * (1.0f / 64.0f)); }
    __syncthreads();

    // phase E: lin, err, out_lat, z_new
    if (tid < 64) {
        float l = (partv[0][tid] + partv[1][tid] + partv[2][tid] + partv[3][tid]) / sc[0];
        lin[tid] = l;
        errv[tid] = (epartv[0][tid] + epartv[1][tid] + epartv[2][tid] + epartv[3][tid]) - u[128 + tid];
        float ps = sc[1];
        outlat[tid] = (1.0f - ps) * u[192 + tid] + ps * l;
        float zn = (1.0f - sc[2]) * zs[tid] + softplusf(u[64 + tid]);
        out[Z_OFF + bh * 64 + tid] = zn;
    }
    __syncthreads();

    // phase F: state update (M_new, S_new) + output projection, float4
    {
        float eta = sc[3], theta = sc[4], oma = 1.0f - sc[2];
        const float4* Sg4 = (const float4*)(S_prev + (size_t)bh * 4096);
        float4* Mo4 = (float4*)(out + M_OFF + (size_t)bh * 4096);
        float4* So4 = (float4*)(out + S_OFF + (size_t)bh * 4096);
        const float4* ev4 = (const float4*)errv;
        for (int idx = tid; idx < 1024; idx += 256) {
            int r = idx >> 4, s4 = idx & 15;
            float kl = u[64 + r];
            float4 e = ev4[s4];
            float4 sg = Sg4[idx];
            float4 ms = Ms4[idx];
            float4 sn;
            sn.x = eta * sg.x - theta * (kl * e.x);
            sn.y = eta * sg.y - theta * (kl * e.y);
            sn.z = eta * sg.z - theta * (kl * e.z);
            sn.w = eta * sg.w - theta * (kl * e.w);
            So4[idx] = sn;
            float4 mn;
            mn.x = oma * ms.x + sn.x;
            mn.y = oma * ms.y + sn.y;
            mn.z = oma * ms.z + sn.z;
            mn.w = oma * ms.w + sn.w;
            Mo4[idx] = mn;
        }
    }
    if (tid < 128) {
        const float4* er = (const float4*)(Ev + ((size_t)h * 128 + tid) * 64);
        const float4* ov = (const float4*)outlat;
        float a = 0.0f;
#pragma unroll
        for (int k = 0; k < 16; ++k) {
            float4 e = er[k], o = ov[k];
            a += e.x * o.x + e.y * o.y + e.z * o.z + e.w * o.w;
        }
        out[OUT_OFF + b * (H_N * D_V) + h * 128 + tid] = a;
    }
}

// ============================================================
extern "C" void kernel_launch(void* const* d_in, const int* in_sizes, int n_in,
                              void* d_out, int out_size) {
    const float* x     = (const float*)d_in[0];
    const float* ln_g  = (const float*)d_in[1];
    const float* ln_b  = (const float*)d_in[2];
    const float* W_qkv = (const float*)d_in[3];
    const float* E_q   = (const float*)d_in[4];
    const float* E_k   = (const float*)d_in[5];
    const float* E_v   = (const float*)d_in[6];
    const float* K_lat = (const float*)d_in[7];
    const float* V_lat = (const float*)d_in[8];
    const float* bm    = (const float*)d_in[9];
    const float* M     = (const float*)d_in[10];
    const float* z     = (const float*)d_in[11];
    const float* S_prev= (const float*)d_in[12];
    const float* r1w   = (const float*)d_in[13];
    const float* r1b   = (const float*)d_in[14];
    const float* r2w   = (const float*)d_in[15];
    const float* r2b   = (const float*)d_in[16];
    const float* g1w   = (const float*)d_in[17];
    const float* g1b   = (const float*)d_in[18];
    const float* g2w   = (const float*)d_in[19];
    const float* g2b   = (const float*)d_in[20];
    const int*   bids  = (const int*)d_in[21];
    const int*   cur   = (const int*)d_in[22];
    float* out = (float*)d_out;

    k_ln<<<B_SZ, 256>>>(x, ln_g, ln_b);
    k_qkv<<<QKV_COLS / 16, 256>>>(W_qkv);
    k_proj<<<B_SZ * H_N, 192>>>(E_q, E_k, E_v);
    k_score<<<NB * B_SZ, 256>>>(bm);
    k_route2<<<B_SZ, 256>>>(bids, cur);
    k_attn<<<B_SZ * H_N, 256>>>(K_lat, V_lat);
    k_tail<<<B_SZ * H_N, 256>>>(M, z, S_prev, r1w, r1b, r2w, r2b,
                                g1w, g1b, g2w, g2b, E_v, out);
}

// round 5
// speedup vs baseline: 1.8612x; 1.1305x over previous
#include <cuda_runtime.h>
#include <cuda_bf16.h>
#include <math.h>

// Problem constants
#define B_SZ 8
#define D_MODEL 2048
#define H_N 16
#define D_H 128
#define D_V 128
#define R_DIM 64
#define W_TOT 8192
#define NB 64
#define QKV_COLS (H_N * (2 * D_H + D_V))   // 6144

// Output layout (concatenated flat float32):
// out (8,2048) | M_new (8,16,64,64) | z_new (8,16,64) | S_new (8,16,64,64)
#define OUT_OFF 0
#define M_OFF   (B_SZ * H_N * D_V)                       // 16384
#define Z_OFF   (M_OFF + B_SZ * H_N * R_DIM * R_DIM)     // 540672
#define S_OFF   (Z_OFF + B_SZ * H_N * R_DIM)             // 548864

#define LOG2_GAMMA (-0.043943347587597055f)   // log2(0.97)

// -------- scratch (device globals; no allocation allowed) --------
__device__ __align__(16) float g_qkv[B_SZ * QKV_COLS];
__device__ __align__(16) float g_part[B_SZ * H_N * NB];  // score partials
__device__ int g_cnt[B_SZ];                               // inter-block barrier

// -------- helpers --------
__device__ __forceinline__ float softplusf(float x) {
    return fmaxf(x, 0.0f) + log1pf(expf(-fabsf(x)));
}
__device__ __forceinline__ float geluf(float x) {
    return 0.5f * x * (1.0f + erff(x * 0.70710678118654752440f));
}
__device__ __forceinline__ float sigmoidf(float x) {
    return 1.0f / (1.0f + expf(-x));
}

// ============================================================
// Kernel 1: fused LayerNorm + qkv GEMM   grid=384, block=256
// Each block computes LN stats redundantly (warp per batch, x is L2-hot),
// applies LN while staging the h tile. Block 0 resets barrier counters.
// ============================================================
__global__ void __launch_bounds__(256) k_qkv_ln(
    const float* __restrict__ x, const float* __restrict__ lg,
    const float* __restrict__ lb, const float* __restrict__ W) {

    __shared__ float4 hs[B_SZ][128];   // 16 KB
    __shared__ float smu[8], sinv[8];
    int tid = threadIdx.x;
    int warp = tid >> 5, lane = tid & 31;
    int colBase = blockIdx.x * 16 + warp * 2;

    if (blockIdx.x == 0 && tid < B_SZ) g_cnt[tid] = 0;

    // LN stats: warp w handles batch w (sum + sumsq over 2048)
    {
        int b = warp;
        const float4* xr = (const float4*)(x + b * D_MODEL);
        float s = 0.0f, ss = 0.0f;
#pragma unroll
        for (int i = 0; i < 16; ++i) {
            float4 v = xr[i * 32 + lane];
            s  += v.x + v.y + v.z + v.w;
            ss += v.x * v.x + v.y * v.y + v.z * v.z + v.w * v.w;
        }
#pragma unroll
        for (int o = 16; o; o >>= 1) {
            s  += __shfl_down_sync(0xffffffffu, s, o);
            ss += __shfl_down_sync(0xffffffffu, ss, o);
        }
        if (lane == 0) {
            float mu = s * (1.0f / D_MODEL);
            float var = ss * (1.0f / D_MODEL) - mu * mu;
            smu[b] = mu;
            sinv[b] = rsqrtf(var + 1e-5f);
        }
    }
    __syncthreads();

    float acc[2][8];
#pragma unroll
    for (int c = 0; c < 2; c++)
#pragma unroll
        for (int b = 0; b < 8; b++) acc[c][b] = 0.0f;

    for (int tile = 0; tile < 4; ++tile) {
        int k0 = tile * 512;
        for (int i = tid; i < 1024; i += 256) {
            int b = i >> 7, kk = i & 127;
            float4 xv = *(const float4*)&x[b * D_MODEL + k0 + kk * 4];
            float4 gv = *(const float4*)&lg[k0 + kk * 4];
            float4 bv = *(const float4*)&lb[k0 + kk * 4];
            float mu = smu[b], inv = sinv[b];
            float4 hv;
            hv.x = (xv.x - mu) * inv * gv.x + bv.x;
            hv.y = (xv.y - mu) * inv * gv.y + bv.y;
            hv.z = (xv.z - mu) * inv * gv.z + bv.z;
            hv.w = (xv.w - mu) * inv * gv.w + bv.w;
            hs[b][kk] = hv;
        }
        __syncthreads();
#pragma unroll
        for (int kk = 0; kk < 4; ++kk) {
            int k4 = lane + kk * 32;
            float4 wv[2];
#pragma unroll
            for (int c = 0; c < 2; c++)
                wv[c] = *(const float4*)(&W[(size_t)(colBase + c) * D_MODEL + k0 + k4 * 4]);
#pragma unroll
            for (int b = 0; b < 8; b++) {
                float4 hv = hs[b][k4];
#pragma unroll
                for (int c = 0; c < 2; c++)
                    acc[c][b] += wv[c].x * hv.x + wv[c].y * hv.y + wv[c].z * hv.z + wv[c].w * hv.w;
            }
        }
        __syncthreads();
    }
#pragma unroll
    for (int c = 0; c < 2; c++)
#pragma unroll
        for (int b = 0; b < 8; b++) {
            float v = acc[c][b];
            for (int o = 16; o; o >>= 1) v += __shfl_down_sync(0xffffffffu, v, o);
            if (lane == 0) g_qkv[b * QKV_COLS + colBase + c] = v;
        }
}

// ============================================================
// Kernel 2: mega — proj + score + barrier + route + attention + tail
// grid=128 (b,h), block=256, 64KB dynamic smem (widx + logit)
// All 128 blocks co-resident (<=148 SMs) => spin barrier is safe.
// ============================================================
__global__ void __launch_bounds__(256) k_mega(
    const float* __restrict__ Kl, const float* __restrict__ Vl,
    const float* __restrict__ bm, const int* __restrict__ bids,
    const int* __restrict__ curp,
    const float* __restrict__ Eq, const float* __restrict__ Ek,
    const float* __restrict__ Ev,
    const float* __restrict__ M, const float* __restrict__ z,
    const float* __restrict__ S_prev,
    const float* __restrict__ r1w, const float* __restrict__ r1b,
    const float* __restrict__ r2w, const float* __restrict__ r2b,
    const float* __restrict__ g1w, const float* __restrict__ g1b,
    const float* __restrict__ g2w, const float* __restrict__ g2b,
    float* __restrict__ out) {

    extern __shared__ __align__(16) char dyn[];
    int*   widx  = (int*)dyn;                   // [8192] 32 KB
    float* logit = (float*)(dyn + W_TOT * 4);   // [8192] 32 KB

    __shared__ __align__(16) float Ms[4096];    // 16 KB
    __shared__ __align__(16) float u[256];      // [QL | KL | VL | attn]
    __shared__ __align__(16) float qf[64], zs[64], errv[64], outlat[64];
    __shared__ __align__(16) float rh[128], gh[256], gout[192];
    __shared__ float partv[4][64];
    __shared__ float epartv[4][64];
    __shared__ float sarr[64];
    __shared__ float red[256];
    __shared__ __align__(16) float accv[16][64];
    __shared__ int warpBase[9];
    __shared__ int s_i1, s_i2;
    __shared__ float s_max, s_sum;
    __shared__ float sc[8];   // 0:qz+eps 1:p_skip 2:alpha 3:eta 4:theta

    int bh = blockIdx.x;
    int b = bh >> 4, h = bh & 15;
    int tid = threadIdx.x;
    int warp = tid >> 5, lane = tid & 31;

    // ---- stage M into smem ----
    {
        const float4* Mg4 = (const float4*)(M + (size_t)bh * 4096);
        float4* Ms4 = (float4*)Ms;
        for (int i = tid; i < 1024; i += 256) Ms4[i] = Mg4[i];
    }

    // ---- latent projections for own (b,h): QL|KL|VL into u[0..191] ----
    if (tid < 192) {
        int which = tid / 64, r = tid & 63;
        const float* vec = g_qkv + b * QKV_COLS + h * 384 + which * 128;
        const float* E = (which == 0 ? Eq : (which == 1 ? Ek : Ev))
                         + (size_t)h * 128 * 64 + r;
        float acc = 0.0f;
#pragma unroll 8
        for (int d = 0; d < 128; ++d) acc += vec[d] * E[d * 64];
        u[which * 64 + r] = acc;
    }
    if (tid < 64) zs[tid] = z[bh * 64 + tid];
    __syncthreads();

    // ---- score partials for own head: 4 threads per node n ----
    {
        int n = tid >> 2, q = tid & 3;
        const float4* mrow = (const float4*)&bm[(((size_t)n * B_SZ + b) * H_N + h) * 64];
        const float4* qv4 = (const float4*)u;   // QL
        float p = 0.0f;
#pragma unroll
        for (int j = 0; j < 4; ++j) {
            float4 mv = mrow[q * 4 + j], qv = qv4[q * 4 + j];
            p += mv.x * qv.x + mv.y * qv.y + mv.z * qv.z + mv.w * qv.w;
        }
        p += __shfl_down_sync(0xffffffffu, p, 2);
        p += __shfl_down_sync(0xffffffffu, p, 1);
        if (q == 0) g_part[(b * H_N + h) * NB + n] = p;
    }
    __threadfence();
    __syncthreads();

    // ---- inter-block barrier among the 16 blocks of batch b ----
    if (tid == 0) {
        atomicAdd(&g_cnt[b], 1);
        volatile int* vc = g_cnt + b;
        while (*vc < H_N) { }
        __threadfence();
    }
    __syncthreads();

    // ---- deterministic fixed-order sum over heads + decay ----
    if (tid < 64) {
        float s = 0.0f;
#pragma unroll
        for (int h2 = 0; h2 < H_N; ++h2)
            s += g_part[(b * H_N + h2) * NB + tid];
        sarr[tid] = s * exp2f((float)(63 - tid) * LOG2_GAMMA) * 0.0078125f;
    }
    __syncthreads();

    // ---- top-2 (lower index wins ties) ----
    if (tid < 32) {
        float v0 = sarr[tid], v1 = sarr[tid + 32];
        float bv; int bi;
        if (v0 >= v1) { bv = v0; bi = tid; } else { bv = v1; bi = tid + 32; }
#pragma unroll
        for (int o = 16; o; o >>= 1) {
            float ov = __shfl_down_sync(0xffffffffu, bv, o);
            int   oi = __shfl_down_sync(0xffffffffu, bi, o);
            if (ov > bv || (ov == bv && oi < bi)) { bv = ov; bi = oi; }
        }
        int i1 = __shfl_sync(0xffffffffu, bi, 0);
        float w0 = (tid == i1)      ? -INFINITY : v0;
        float w1 = (tid + 32 == i1) ? -INFINITY : v1;
        float cv; int ci;
        if (w0 >= w1) { cv = w0; ci = tid; } else { cv = w1; ci = tid + 32; }
#pragma unroll
        for (int o = 16; o; o >>= 1) {
            float ov = __shfl_down_sync(0xffffffffu, cv, o);
            int   oi = __shfl_down_sync(0xffffffffu, ci, o);
            if (ov > cv || (ov == cv && oi < ci)) { cv = ov; ci = oi; }
        }
        if (tid == 0) { s_i1 = i1; s_i2 = ci; }
    }
    __syncthreads();

    // ---- deterministic compaction into smem widx ----
    int cur = curp[0];
    {
        int i1 = s_i1, i2 = s_i2;
        const int* br = bids + b * W_TOT;
        int wbase = warp * 1024;
        int cnt = 0;
#pragma unroll 4
        for (int j = 0; j < 32; ++j) {
            int id = br[wbase + j * 32 + lane];
            unsigned bal = __ballot_sync(0xffffffffu, id == i1 || id == i2 || id == cur);
            cnt += __popc(bal);
        }
        if (lane == 0) warpBase[warp] = cnt;
        __syncthreads();
        if (tid == 0) {
            int t = 0;
#pragma unroll
            for (int k = 0; k < 8; ++k) { int c = warpBase[k]; warpBase[k] = t; t += c; }
            warpBase[8] = t;
        }
        __syncthreads();
        int off = warpBase[warp];
        unsigned lmask = (1u << lane) - 1u;
        for (int j = 0; j < 32; ++j) {
            int w = wbase + j * 32 + lane;
            int id = br[w];
            bool m = (id == i1 || id == i2 || id == cur);
            unsigned bal = __ballot_sync(0xffffffffu, m);
            if (m) widx[off + __popc(bal & lmask)] = w;
            off += __popc(bal);
        }
    }
    __syncthreads();
    int nw = warpBase[8];

    // ---- attention: logits + max ----
    {
        const float4* qr = (const float4*)u;   // QL
        float lm = -INFINITY;
        for (int i = tid; i < nw; i += 256) {
            int w = widx[i];
            const float4* kr = (const float4*)&Kl[((size_t)bh * W_TOT + w) * 64];
            float d = 0.0f;
#pragma unroll
            for (int r4 = 0; r4 < 16; ++r4) {
                float4 kv = kr[r4], qv = qr[r4];
                d += kv.x * qv.x + kv.y * qv.y + kv.z * qv.z + kv.w * qv.w;
            }
            d *= 0.125f;   // 1/sqrt(64)
            logit[i] = d;
            lm = fmaxf(lm, d);
        }
        red[tid] = lm; __syncthreads();
        for (int o = 128; o; o >>= 1) { if (tid < o) red[tid] = fmaxf(red[tid], red[tid + o]); __syncthreads(); }
        if (tid == 0) s_max = red[0];
        __syncthreads();

        float mx = s_max;
        float ls = 0.0f;
        for (int i = tid; i < nw; i += 256) {
            float e = expf(logit[i] - mx);
            logit[i] = e;
            ls += e;
        }
        red[tid] = ls; __syncthreads();
        for (int o = 128; o; o >>= 1) { if (tid < o) red[tid] += red[tid + o]; __syncthreads(); }
        if (tid == 0) s_sum = red[0];
        __syncthreads();

        int r4 = tid & 15, g = tid >> 4;
        float4 a4 = make_float4(0.0f, 0.0f, 0.0f, 0.0f);
        for (int i = g; i < nw; i += 16) {
            int w = widx[i];
            float pw = logit[i];
            float4 v = *(const float4*)&Vl[((size_t)bh * W_TOT + w) * 64 + r4 * 4];
            a4.x += pw * v.x; a4.y += pw * v.y; a4.z += pw * v.z; a4.w += pw * v.w;
        }
        *(float4*)&accv[g][r4 * 4] = a4;
        __syncthreads();
        if (tid < 64) {
            float a = 0.0f;
#pragma unroll
            for (int gg = 0; gg < 16; ++gg) a += accv[gg][tid];
            u[192 + tid] = a / s_sum;   // attn
        }
    }
    __syncthreads();

    // ================= tail =================
    // phase B: qf, rh, gh
    if (tid < 64) qf[tid] = softplusf(u[tid]);
    if (tid < 128) {
        const float4* wr = (const float4*)(r1w + tid * 64);
        const float4* qv = (const float4*)u;
        float a = r1b[tid];
#pragma unroll
        for (int k = 0; k < 16; ++k) {
            float4 wv = wr[k], uv = qv[k];
            a += wv.x * uv.x + wv.y * uv.y + wv.z * uv.z + wv.w * uv.w;
        }
        rh[tid] = geluf(a);
    }
    {
        const float4* wr = (const float4*)(g1w + (size_t)tid * 256);
        const float4* uv4 = (const float4*)u;
        float a = g1b[tid];
#pragma unroll
        for (int k = 0; k < 64; ++k) {
            float4 wv = wr[k], uv = uv4[k];
            a += wv.x * uv.x + wv.y * uv.y + wv.z * uv.z + wv.w * uv.w;
        }
        gh[tid] = geluf(a);
    }
    __syncthreads();

    // phase C: lin partials, err partials, gout
    {
        int s = tid & 63, g = tid >> 6;
        float a = 0.0f, e = 0.0f;
        for (int r = g; r < 64; r += 4) {
            float mrs = Ms[r * 64 + s];
            a += qf[r] * mrs;
            e += u[64 + r] * mrs;   // K_L @ M
        }
        partv[g][s] = a;
        epartv[g][s] = e;
    }
    if (tid < 192) {
        const float4* wr = (const float4*)(g2w + (size_t)tid * 256);
        const float4* gv4 = (const float4*)gh;
        float a = g2b[tid];
#pragma unroll
        for (int k = 0; k < 64; ++k) {
            float4 wv = wr[k], gv = gv4[k];
            a += wv.x * gv.x + wv.y * gv.y + wv.z * gv.z + wv.w * gv.w;
        }
        gout[tid] = a;
    }
    __syncthreads();

    // phase D: scalar reductions
    if (tid == 0) { float t = 0.0f; for (int k = 0; k < 64; ++k) t += qf[k] * zs[k]; sc[0] = t + 1e-6f; }
    if (tid == 1) { float t = r2b[0]; for (int k = 0; k < 128; ++k) t += rh[k] * r2w[k]; sc[1] = sigmoidf(t); }
    if (tid == 2) { float t = 0.0f; for (int k = 0; k < 64; ++k) t += gout[k]; sc[2] = sigmoidf(t * (1.0f / 64.0f)); }
    if (tid == 3) { float t = 0.0f; for (int k = 0; k < 64; ++k) t += gout[64 + k]; sc[3] = softplusf(t * (1.0f / 64.0f)); }
    if (tid == 4) { float t = 0.0f; for (int k = 0; k < 64; ++k) t += gout[128 + k]; sc[4] = softplusf(t * (1.0f / 64.0f)); }
    __syncthreads();

    // phase E: lin, err, out_lat, z_new
    if (tid < 64) {
        float l = (partv[0][tid] + partv[1][tid] + partv[2][tid] + partv[3][tid]) / sc[0];
        errv[tid] = (epartv[0][tid] + epartv[1][tid] + epartv[2][tid] + epartv[3][tid]) - u[128 + tid];
        float ps = sc[1];
        outlat[tid] = (1.0f - ps) * u[192 + tid] + ps * l;
        float zn = (1.0f - sc[2]) * zs[tid] + softplusf(u[64 + tid]);
        out[Z_OFF + bh * 64 + tid] = zn;
    }
    __syncthreads();

    // phase F: state update (M_new, S_new) + output projection
    {
        float eta = sc[3], theta = sc[4], oma = 1.0f - sc[2];
        const float4* Sg4 = (const float4*)(S_prev + (size_t)bh * 4096);
        float4* Mo4 = (float4*)(out + M_OFF + (size_t)bh * 4096);
        float4* So4 = (float4*)(out + S_OFF + (size_t)bh * 4096);
        const float4* ev4 = (const float4*)errv;
        const float4* Ms4 = (const float4*)Ms;
        for (int idx = tid; idx < 1024; idx += 256) {
            int r = idx >> 4, s4 = idx & 15;
            float kl = u[64 + r];
            float4 e = ev4[s4];
            float4 sg = Sg4[idx];
            float4 ms = Ms4[idx];
            float4 sn;
            sn.x = eta * sg.x - theta * (kl * e.x);
            sn.y = eta * sg.y - theta * (kl * e.y);
            sn.z = eta * sg.z - theta * (kl * e.z);
            sn.w = eta * sg.w - theta * (kl * e.w);
            So4[idx] = sn;
            float4 mn;
            mn.x = oma * ms.x + sn.x;
            mn.y = oma * ms.y + sn.y;
            mn.z = oma * ms.z + sn.z;
            mn.w = oma * ms.w + sn.w;
            Mo4[idx] = mn;
        }
    }
    if (tid < 128) {
        const float4* er = (const float4*)(Ev + ((size_t)h * 128 + tid) * 64);
        const float4* ov = (const float4*)outlat;
        float a = 0.0f;
#pragma unroll
        for (int k = 0; k < 16; ++k) {
            float4 e = er[k], o = ov[k];
            a += e.x * o.x + e.y * o.y + e.z * o.z + e.w * o.w;
        }
        out[OUT_OFF + b * (H_N * D_V) + h * 128 + tid] = a;
    }
}

// ============================================================
extern "C" void kernel_launch(void* const* d_in, const int* in_sizes, int n_in,
                              void* d_out, int out_size) {
    const float* x     = (const float*)d_in[0];
    const float* ln_g  = (const float*)d_in[1];
    const float* ln_b  = (const float*)d_in[2];
    const float* W_qkv = (const float*)d_in[3];
    const float* E_q   = (const float*)d_in[4];
    const float* E_k   = (const float*)d_in[5];
    const float* E_v   = (const float*)d_in[6];
    const float* K_lat = (const float*)d_in[7];
    const float* V_lat = (const float*)d_in[8];
    const float* bm    = (const float*)d_in[9];
    const float* M     = (const float*)d_in[10];
    const float* z     = (const float*)d_in[11];
    const float* S_prev= (const float*)d_in[12];
    const float* r1w   = (const float*)d_in[13];
    const float* r1b   = (const float*)d_in[14];
    const float* r2w   = (const float*)d_in[15];
    const float* r2b   = (const float*)d_in[16];
    const float* g1w   = (const float*)d_in[17];
    const float* g1b   = (const float*)d_in[18];
    const float* g2w   = (const float*)d_in[19];
    const float* g2b   = (const float*)d_in[20];
    const int*   bids  = (const int*)d_in[21];
    const int*   cur   = (const int*)d_in[22];
    float* out = (float*)d_out;

    static bool attr_done = false;
    if (!attr_done) {
        cudaFuncSetAttribute(k_mega, cudaFuncAttributeMaxDynamicSharedMemorySize,
                             W_TOT * 8);
        attr_done = true;
    }

    k_qkv_ln<<<QKV_COLS / 16, 256>>>(x, ln_g, ln_b, W_qkv);
    k_mega<<<B_SZ * H_N, 256, W_TOT * 8>>>(K_lat, V_lat, bm, bids, cur,
                                           E_q, E_k, E_v, M, z, S_prev,
                                           r1w, r1b, r2w, r2b,
                                           g1w, g1b, g2w, g2b, out);
}

// round 6
// speedup vs baseline: 1.9278x; 1.0358x over previous
#include <cuda_runtime.h>
#include <cuda_bf16.h>
#include <math.h>

// Problem constants
#define B_SZ 8
#define D_MODEL 2048
#define H_N 16
#define D_H 128
#define D_V 128
#define R_DIM 64
#define W_TOT 8192
#define NB 64
#define QKV_COLS (H_N * (2 * D_H + D_V))   // 6144

// Output layout (concatenated flat float32):
#define OUT_OFF 0
#define M_OFF   (B_SZ * H_N * D_V)                       // 16384
#define Z_OFF   (M_OFF + B_SZ * H_N * R_DIM * R_DIM)     // 540672
#define S_OFF   (Z_OFF + B_SZ * H_N * R_DIM)             // 548864

#define LOG2_GAMMA (-0.043943347587597055f)   // log2(0.97)
#define FULL 0xffffffffu

// -------- scratch (device globals; no allocation allowed) --------
__device__ __align__(16) float g_qkv[B_SZ * QKV_COLS];
__device__ __align__(16) float g_part[B_SZ * H_N * NB];  // score partials
__device__ int g_cnt[B_SZ];                               // inter-block barrier

// -------- helpers --------
__device__ __forceinline__ float softplusf(float x) {
    return fmaxf(x, 0.0f) + log1pf(expf(-fabsf(x)));
}
__device__ __forceinline__ float geluf(float x) {
    return 0.5f * x * (1.0f + erff(x * 0.70710678118654752440f));
}
__device__ __forceinline__ float sigmoidf(float x) {
    return 1.0f / (1.0f + expf(-x));
}

// ============================================================
// Kernel 1: fused LayerNorm + qkv GEMM   grid=384, block=256
// ============================================================
__global__ void __launch_bounds__(256) k_qkv_ln(
    const float* __restrict__ x, const float* __restrict__ lg,
    const float* __restrict__ lb, const float* __restrict__ W) {

    __shared__ float4 hs[B_SZ][128];   // 16 KB
    __shared__ float smu[8], sinv[8];
    int tid = threadIdx.x;
    int warp = tid >> 5, lane = tid & 31;
    int colBase = blockIdx.x * 16 + warp * 2;

    if (blockIdx.x == 0 && tid < B_SZ) g_cnt[tid] = 0;

    {
        int b = warp;
        const float4* xr = (const float4*)(x + b * D_MODEL);
        float s = 0.0f, ss = 0.0f;
#pragma unroll
        for (int i = 0; i < 16; ++i) {
            float4 v = xr[i * 32 + lane];
            s  += v.x + v.y + v.z + v.w;
            ss += v.x * v.x + v.y * v.y + v.z * v.z + v.w * v.w;
        }
#pragma unroll
        for (int o = 16; o; o >>= 1) {
            s  += __shfl_down_sync(FULL, s, o);
            ss += __shfl_down_sync(FULL, ss, o);
        }
        if (lane == 0) {
            float mu = s * (1.0f / D_MODEL);
            float var = ss * (1.0f / D_MODEL) - mu * mu;
            smu[b] = mu;
            sinv[b] = rsqrtf(var + 1e-5f);
        }
    }
    __syncthreads();

    float acc[2][8];
#pragma unroll
    for (int c = 0; c < 2; c++)
#pragma unroll
        for (int b = 0; b < 8; b++) acc[c][b] = 0.0f;

    for (int tile = 0; tile < 4; ++tile) {
        int k0 = tile * 512;
        for (int i = tid; i < 1024; i += 256) {
            int b = i >> 7, kk = i & 127;
            float4 xv = *(const float4*)&x[b * D_MODEL + k0 + kk * 4];
            float4 gv = *(const float4*)&lg[k0 + kk * 4];
            float4 bv = *(const float4*)&lb[k0 + kk * 4];
            float mu = smu[b], inv = sinv[b];
            float4 hv;
            hv.x = (xv.x - mu) * inv * gv.x + bv.x;
            hv.y = (xv.y - mu) * inv * gv.y + bv.y;
            hv.z = (xv.z - mu) * inv * gv.z + bv.z;
            hv.w = (xv.w - mu) * inv * gv.w + bv.w;
            hs[b][kk] = hv;
        }
        __syncthreads();
#pragma unroll
        for (int kk = 0; kk < 4; ++kk) {
            int k4 = lane + kk * 32;
            float4 wv[2];
#pragma unroll
            for (int c = 0; c < 2; c++)
                wv[c] = *(const float4*)(&W[(size_t)(colBase + c) * D_MODEL + k0 + k4 * 4]);
#pragma unroll
            for (int b = 0; b < 8; b++) {
                float4 hv = hs[b][k4];
#pragma unroll
                for (int c = 0; c < 2; c++)
                    acc[c][b] += wv[c].x * hv.x + wv[c].y * hv.y + wv[c].z * hv.z + wv[c].w * hv.w;
            }
        }
        __syncthreads();
    }
#pragma unroll
    for (int c = 0; c < 2; c++)
#pragma unroll
        for (int b = 0; b < 8; b++) {
            float v = acc[c][b];
            for (int o = 16; o; o >>= 1) v += __shfl_down_sync(FULL, v, o);
            if (lane == 0) g_qkv[b * QKV_COLS + colBase + c] = v;
        }
}

// ============================================================
// Kernel 2: mega   grid=128 (b,h), block=512, 64KB dynamic smem
// ============================================================
__global__ void __launch_bounds__(512) k_mega(
    const float* __restrict__ Kl, const float* __restrict__ Vl,
    const float* __restrict__ bm, const int* __restrict__ bids,
    const int* __restrict__ curp,
    const float* __restrict__ Eq, const float* __restrict__ Ek,
    const float* __restrict__ Ev,
    const float* __restrict__ M, const float* __restrict__ z,
    const float* __restrict__ S_prev,
    const float* __restrict__ r1w, const float* __restrict__ r1b,
    const float* __restrict__ r2w, const float* __restrict__ r2b,
    const float* __restrict__ g1w, const float* __restrict__ g1b,
    const float* __restrict__ g2w, const float* __restrict__ g2b,
    float* __restrict__ out) {

    extern __shared__ __align__(16) char dyn[];
    int*   widx  = (int*)dyn;                   // [8192] 32 KB
    float* logit = (float*)(dyn + W_TOT * 4);   // [8192] 32 KB (doubles as bids stage)
    int*   bidsS = (int*)(dyn + W_TOT * 4);     // alias: staged bids (pre-logit)

    __shared__ __align__(16) float Ms[4096];    // 16 KB
    __shared__ __align__(16) float u[256];      // [QL | KL | VL | attn]
    __shared__ __align__(16) float qf[64], zs[64], errv[64], outlat[64];
    __shared__ __align__(16) float rh[128], gh[256], gout[192];
    __shared__ float partv[8][64];
    __shared__ float epartv[8][64];
    __shared__ float sarr[64];
    __shared__ float red[512];
    __shared__ __align__(16) float accv[32][64];  // 8 KB
    __shared__ int warpCnt[16];
    __shared__ int warpBase[17];
    __shared__ int s_i1, s_i2;
    __shared__ float s_max, s_sum;
    __shared__ float sc[8];

    int bh = blockIdx.x;
    int b = bh >> 4, h = bh & 15;
    int tid = threadIdx.x;
    int warp = tid >> 5, lane = tid & 31;

    // ===== phase 1: projections (warps 0-11) + bids staging (warps 12-15) =====
    if (tid < 384) {
        int o = tid >> 1;          // 0..191
        int half = tid & 1;
        int which = o >> 6, r = o & 63;
        const float* vec = g_qkv + b * QKV_COLS + h * 384 + which * 128 + half * 64;
        const float* E = (which == 0 ? Eq : (which == 1 ? Ek : Ev))
                         + (size_t)h * 8192 + (half * 64) * 64 + r;
        float acc = 0.0f;
#pragma unroll 8
        for (int d = 0; d < 64; ++d) acc += vec[d] * E[d * 64];
        acc += __shfl_down_sync(FULL, acc, 1);
        if (half == 0) u[o] = acc;
    } else {
        const int4* br4 = (const int4*)(bids + b * W_TOT);
        int4* bs4 = (int4*)bidsS;
        int t = tid - 384;
#pragma unroll
        for (int k = 0; k < 16; ++k) bs4[t + k * 128] = br4[t + k * 128];
    }
    __syncthreads();

    // ===== phase 2: score partials (tid<256) | M staging + z (tid>=256) =====
    if (tid < 256) {
        int n = tid >> 2, q = tid & 3;
        const float4* mrow = (const float4*)&bm[(((size_t)n * B_SZ + b) * H_N + h) * 64];
        const float4* qv4 = (const float4*)u;   // QL
        float p = 0.0f;
#pragma unroll
        for (int j = 0; j < 4; ++j) {
            float4 mv = mrow[q * 4 + j], qv = qv4[q * 4 + j];
            p += mv.x * qv.x + mv.y * qv.y + mv.z * qv.z + mv.w * qv.w;
        }
        p += __shfl_down_sync(FULL, p, 2);
        p += __shfl_down_sync(FULL, p, 1);
        if (q == 0) g_part[(b * H_N + h) * NB + n] = p;
        __threadfence();
    } else {
        const float4* Mg4 = (const float4*)(M + (size_t)bh * 4096);
        float4* Ms4 = (float4*)Ms;
        int t = tid - 256;
#pragma unroll
        for (int k = 0; k < 4; ++k) Ms4[t + k * 256] = Mg4[t + k * 256];
        if (t < 64) zs[t] = z[bh * 64 + t];
    }
    __syncthreads();

    // ===== inter-block barrier among the 16 blocks of batch b =====
    if (tid == 0) {
        atomicAdd(&g_cnt[b], 1);
        volatile int* vc = g_cnt + b;
        while (*vc < H_N) { }
        __threadfence();
    }
    __syncthreads();

    // ===== sum partials + decay, top-2 =====
    if (tid < 64) {
        float s = 0.0f;
#pragma unroll
        for (int h2 = 0; h2 < H_N; ++h2)
            s += g_part[(b * H_N + h2) * NB + tid];
        sarr[tid] = s * exp2f((float)(63 - tid) * LOG2_GAMMA) * 0.0078125f;
    }
    __syncthreads();
    if (tid < 32) {
        float v0 = sarr[tid], v1 = sarr[tid + 32];
        float bv; int bi;
        if (v0 >= v1) { bv = v0; bi = tid; } else { bv = v1; bi = tid + 32; }
#pragma unroll
        for (int o = 16; o; o >>= 1) {
            float ov = __shfl_down_sync(FULL, bv, o);
            int   oi = __shfl_down_sync(FULL, bi, o);
            if (ov > bv || (ov == bv && oi < bi)) { bv = ov; bi = oi; }
        }
        int i1 = __shfl_sync(FULL, bi, 0);
        float w0 = (tid == i1)      ? -INFINITY : v0;
        float w1 = (tid + 32 == i1) ? -INFINITY : v1;
        float cv; int ci;
        if (w0 >= w1) { cv = w0; ci = tid; } else { cv = w1; ci = tid + 32; }
#pragma unroll
        for (int o = 16; o; o >>= 1) {
            float ov = __shfl_down_sync(FULL, cv, o);
            int   oi = __shfl_down_sync(FULL, ci, o);
            if (ov > cv || (ov == cv && oi < ci)) { cv = ov; ci = oi; }
        }
        if (tid == 0) { s_i1 = i1; s_i2 = ci; }
    }
    __syncthreads();

    // ===== compaction from smem: 16 entries/thread, register mask + warp scan =====
    int nw;
    {
        int i1 = s_i1, i2 = s_i2, cur = curp[0];
        const int4* bs4 = (const int4*)bidsS;
        unsigned mbits = 0;
        int c = 0;
#pragma unroll
        for (int k = 0; k < 4; ++k) {
            int4 v = bs4[tid * 4 + k];
            if (v.x == i1 || v.x == i2 || v.x == cur) { mbits |= 1u << (k * 4 + 0); c++; }
            if (v.y == i1 || v.y == i2 || v.y == cur) { mbits |= 1u << (k * 4 + 1); c++; }
            if (v.z == i1 || v.z == i2 || v.z == cur) { mbits |= 1u << (k * 4 + 2); c++; }
            if (v.w == i1 || v.w == i2 || v.w == cur) { mbits |= 1u << (k * 4 + 3); c++; }
        }
        // warp inclusive scan of counts
        int inc = c;
#pragma unroll
        for (int o = 1; o < 32; o <<= 1) {
            int t = __shfl_up_sync(FULL, inc, o);
            if (lane >= o) inc += t;
        }
        if (lane == 31) warpCnt[warp] = inc;
        __syncthreads();
        if (tid == 0) {
            int t = 0;
#pragma unroll
            for (int k = 0; k < 16; ++k) { warpBase[k] = t; t += warpCnt[k]; }
            warpBase[16] = t;
        }
        __syncthreads();
        int off = warpBase[warp] + (inc - c);
        int base = tid * 16;
#pragma unroll
        for (int j = 0; j < 16; ++j)
            if ((mbits >> j) & 1u) widx[off++] = base + j;
        nw = warpBase[16];
    }
    __syncthreads();   // widx done; logit region free to overwrite

    // ===== attention =====
    {
        const float4* qr = (const float4*)u;   // QL
        float lm = -INFINITY;
        for (int i = tid; i < nw; i += 512) {
            int w = widx[i];
            const float4* kr = (const float4*)&Kl[((size_t)bh * W_TOT + w) * 64];
            float d = 0.0f;
#pragma unroll
            for (int r4 = 0; r4 < 16; ++r4) {
                float4 kv = kr[r4], qv = qr[r4];
                d += kv.x * qv.x + kv.y * qv.y + kv.z * qv.z + kv.w * qv.w;
            }
            d *= 0.125f;
            logit[i] = d;
            lm = fmaxf(lm, d);
        }
        red[tid] = lm; __syncthreads();
        for (int o = 256; o; o >>= 1) { if (tid < o) red[tid] = fmaxf(red[tid], red[tid + o]); __syncthreads(); }
        if (tid == 0) s_max = red[0];
        __syncthreads();

        float mx = s_max;
        float ls = 0.0f;
        for (int i = tid; i < nw; i += 512) {
            float e = expf(logit[i] - mx);
            logit[i] = e;
            ls += e;
        }
        red[tid] = ls; __syncthreads();
        for (int o = 256; o; o >>= 1) { if (tid < o) red[tid] += red[tid + o]; __syncthreads(); }
        if (tid == 0) s_sum = red[0];
        __syncthreads();

        int r4 = tid & 15, g = tid >> 4;   // 32 groups
        float4 a4 = make_float4(0.0f, 0.0f, 0.0f, 0.0f);
        for (int i = g; i < nw; i += 32) {
            int w = widx[i];
            float pw = logit[i];
            float4 v = *(const float4*)&Vl[((size_t)bh * W_TOT + w) * 64 + r4 * 4];
            a4.x += pw * v.x; a4.y += pw * v.y; a4.z += pw * v.z; a4.w += pw * v.w;
        }
        *(float4*)&accv[g][r4 * 4] = a4;
        __syncthreads();
        if (tid < 64) {
            float a = 0.0f;
#pragma unroll
            for (int gg = 0; gg < 32; ++gg) a += accv[gg][tid];
            u[192 + tid] = a / s_sum;
        }
    }
    __syncthreads();

    // ===== tail =====
    // qf, rh (128 thr), gh (2 thr/output)
    if (tid < 64) qf[tid] = softplusf(u[tid]);
    {
        int o = tid >> 1, half = tid & 1;
        const float4* wr = (const float4*)(g1w + (size_t)o * 256 + half * 128);
        const float4* uv4 = (const float4*)u + half * 32;
        float a = 0.0f;
#pragma unroll
        for (int k = 0; k < 32; ++k) {
            float4 wv = wr[k], uv = uv4[k];
            a += wv.x * uv.x + wv.y * uv.y + wv.z * uv.z + wv.w * uv.w;
        }
        a += __shfl_down_sync(FULL, a, 1);
        if (half == 0) gh[o] = geluf(a + g1b[o]);
    }
    if (tid >= 256 && tid < 384) {
        int o = tid - 256;
        const float4* wr = (const float4*)(r1w + o * 64);
        const float4* qv = (const float4*)u;
        float a = r1b[o];
#pragma unroll
        for (int k = 0; k < 16; ++k) {
            float4 wv = wr[k], uv = qv[k];
            a += wv.x * uv.x + wv.y * uv.y + wv.z * uv.z + wv.w * uv.w;
        }
        rh[o] = geluf(a);
    }
    __syncthreads();

    // lin/err partials (8 groups) + gout (2 thr/output on tid<384)
    {
        int s = tid & 63, g = tid >> 6;   // 0..7
        float a = 0.0f, e = 0.0f;
        for (int r = g; r < 64; r += 8) {
            float mrs = Ms[r * 64 + s];
            a += qf[r] * mrs;
            e += u[64 + r] * mrs;
        }
        partv[g][s] = a;
        epartv[g][s] = e;
    }
    if (tid < 384) {
        int o = tid >> 1, half = tid & 1;
        const float4* wr = (const float4*)(g2w + (size_t)o * 256 + half * 128);
        const float4* gv4 = (const float4*)gh + half * 32;
        float a = 0.0f;
#pragma unroll
        for (int k = 0; k < 32; ++k) {
            float4 wv = wr[k], gv = gv4[k];
            a += wv.x * gv.x + wv.y * gv.y + wv.z * gv.z + wv.w * gv.w;
        }
        a += __shfl_down_sync(FULL, a, 1);
        if (half == 0) gout[o] = a + g2b[o];
    }
    __syncthreads();

    // scalar reductions
    if (tid == 0) { float t = 0.0f; for (int k = 0; k < 64; ++k) t += qf[k] * zs[k]; sc[0] = t + 1e-6f; }
    if (tid == 1) { float t = r2b[0]; for (int k = 0; k < 128; ++k) t += rh[k] * r2w[k]; sc[1] = sigmoidf(t); }
    if (tid == 2) { float t = 0.0f; for (int k = 0; k < 64; ++k) t += gout[k]; sc[2] = sigmoidf(t * (1.0f / 64.0f)); }
    if (tid == 3) { float t = 0.0f; for (int k = 0; k < 64; ++k) t += gout[64 + k]; sc[3] = softplusf(t * (1.0f / 64.0f)); }
    if (tid == 4) { float t = 0.0f; for (int k = 0; k < 64; ++k) t += gout[128 + k]; sc[4] = softplusf(t * (1.0f / 64.0f)); }
    __syncthreads();

    // lin, err, out_lat, z_new
    if (tid < 64) {
        float l = 0.0f, e = 0.0f;
#pragma unroll
        for (int g = 0; g < 8; ++g) { l += partv[g][tid]; e += epartv[g][tid]; }
        l /= sc[0];
        errv[tid] = e - u[128 + tid];
        float ps = sc[1];
        outlat[tid] = (1.0f - ps) * u[192 + tid] + ps * l;
        float zn = (1.0f - sc[2]) * zs[tid] + softplusf(u[64 + tid]);
        out[Z_OFF + bh * 64 + tid] = zn;
    }
    __syncthreads();

    // state update + output projection
    {
        float eta = sc[3], theta = sc[4], oma = 1.0f - sc[2];
        const float4* Sg4 = (const float4*)(S_prev + (size_t)bh * 4096);
        float4* Mo4 = (float4*)(out + M_OFF + (size_t)bh * 4096);
        float4* So4 = (float4*)(out + S_OFF + (size_t)bh * 4096);
        const float4* ev4 = (const float4*)errv;
        const float4* Ms4 = (const float4*)Ms;
#pragma unroll
        for (int k = 0; k < 2; ++k) {
            int idx = tid + k * 512;
            int r = idx >> 4, s4 = idx & 15;
            float kl = u[64 + r];
            float4 e = ev4[s4];
            float4 sg = Sg4[idx];
            float4 ms = Ms4[idx];
            float4 sn;
            sn.x = eta * sg.x - theta * (kl * e.x);
            sn.y = eta * sg.y - theta * (kl * e.y);
            sn.z = eta * sg.z - theta * (kl * e.z);
            sn.w = eta * sg.w - theta * (kl * e.w);
            So4[idx] = sn;
            float4 mn;
            mn.x = oma * ms.x + sn.x;
            mn.y = oma * ms.y + sn.y;
            mn.z = oma * ms.z + sn.z;
            mn.w = oma * ms.w + sn.w;
            Mo4[idx] = mn;
        }
    }
    if (tid < 256) {
        int o = tid >> 1, half = tid & 1;
        const float4* er = (const float4*)(Ev + ((size_t)h * 128 + o) * 64) + half * 8;
        const float4* ov = (const float4*)outlat + half * 8;
        float a = 0.0f;
#pragma unroll
        for (int k = 0; k < 8; ++k) {
            float4 e = er[k], oo = ov[k];
            a += e.x * oo.x + e.y * oo.y + e.z * oo.z + e.w * oo.w;
        }
        a += __shfl_down_sync(FULL, a, 1);
        if (half == 0) out[OUT_OFF + b * (H_N * D_V) + h * 128 + o] = a;
    }
}

// ============================================================
extern "C" void kernel_launch(void* const* d_in, const int* in_sizes, int n_in,
                              void* d_out, int out_size) {
    const float* x     = (const float*)d_in[0];
    const float* ln_g  = (const float*)d_in[1];
    const float* ln_b  = (const float*)d_in[2];
    const float* W_qkv = (const float*)d_in[3];
    const float* E_q   = (const float*)d_in[4];
    const float* E_k   = (const float*)d_in[5];
    const float* E_v   = (const float*)d_in[6];
    const float* K_lat = (const float*)d_in[7];
    const float* V_lat = (const float*)d_in[8];
    const float* bm    = (const float*)d_in[9];
    const float* M     = (const float*)d_in[10];
    const float* z     = (const float*)d_in[11];
    const float* S_prev= (const float*)d_in[12];
    const float* r1w   = (const float*)d_in[13];
    const float* r1b   = (const float*)d_in[14];
    const float* r2w   = (const float*)d_in[15];
    const float* r2b   = (const float*)d_in[16];
    const float* g1w   = (const float*)d_in[17];
    const float* g1b   = (const float*)d_in[18];
    const float* g2w   = (const float*)d_in[19];
    const float* g2b   = (const float*)d_in[20];
    const int*   bids  = (const int*)d_in[21];
    const int*   cur   = (const int*)d_in[22];
    float* out = (float*)d_out;

    static bool attr_done = false;
    if (!attr_done) {
        cudaFuncSetAttribute(k_mega, cudaFuncAttributeMaxDynamicSharedMemorySize,
                             W_TOT * 8);
        attr_done = true;
    }

    k_qkv_ln<<<QKV_COLS / 16, 256>>>(x, ln_g, ln_b, W_qkv);
    k_mega<<<B_SZ * H_N, 512, W_TOT * 8>>>(K_lat, V_lat, bm, bids, cur,
                                           E_q, E_k, E_v, M, z, S_prev,
                                           r1w, r1b, r2w, r2b,
                                           g1w, g1b, g2w, g2b, out);
}

// round 7
// speedup vs baseline: 2.0682x; 1.0728x over previous
#include <cuda_runtime.h>
#include <cuda_bf16.h>
#include <math.h>

#define B_SZ 8
#define D_MODEL 2048
#define H_N 16
#define R_DIM 64
#define W_TOT 8192
#define NB 64
#define QKV_COLS 6144

#define OUT_OFF 0
#define M_OFF   (B_SZ * H_N * 128)                       // 16384
#define Z_OFF   (M_OFF + B_SZ * H_N * R_DIM * R_DIM)     // 540672
#define S_OFF   (Z_OFF + B_SZ * H_N * R_DIM)             // 548864

#define LOG2_GAMMA (-0.043943347587597055f)
#define FULL 0xffffffffu

// -------- scratch (device globals; zero-initialized, never reset) --------
__device__ __align__(16) float g_qkv[B_SZ * QKV_COLS];
__device__ __align__(16) float g_part[B_SZ * H_N * NB];
__device__ int g_cnt1;          // global barrier ticket counter (monotone)
__device__ int g_cntB[B_SZ];    // per-batch barrier ticket counters (monotone)

__device__ __forceinline__ float softplusf(float x) {
    return fmaxf(x, 0.0f) + log1pf(expf(-fabsf(x)));
}
__device__ __forceinline__ float geluf(float x) {
    return 0.5f * x * (1.0f + erff(x * 0.70710678118654752440f));
}
__device__ __forceinline__ float sigmoidf(float x) {
    return 1.0f / (1.0f + expf(-x));
}

// ============================================================
// ONE kernel: staging || LN+QKV GEMM -> barrier1 -> proj+score
// -> arrive(batch) -> tail-prep -> wait -> route+attn+tail
// grid=128 (b,h), block=512, 64KB dynamic smem
// ============================================================
__global__ void __launch_bounds__(512) k_all(
    const float* __restrict__ x, const float* __restrict__ lg,
    const float* __restrict__ lb, const float* __restrict__ W,
    const float* __restrict__ Kl, const float* __restrict__ Vl,
    const float* __restrict__ bm, const int* __restrict__ bids,
    const int* __restrict__ curp,
    const float* __restrict__ Eq, const float* __restrict__ Ek,
    const float* __restrict__ Ev,
    const float* __restrict__ M, const float* __restrict__ z,
    const float* __restrict__ S_prev,
    const float* __restrict__ r1w, const float* __restrict__ r1b,
    const float* __restrict__ r2w, const float* __restrict__ r2b,
    const float* __restrict__ g1w, const float* __restrict__ g1b,
    const float* __restrict__ g2w, const float* __restrict__ g2b,
    float* __restrict__ out) {

    extern __shared__ __align__(16) char dyn[];
    float4* hs4  = (float4*)dyn;                 // [1024] during qkv phase
    int*   widx  = (int*)dyn;                    // [8192] after barrier-2
    int*   bidsS = (int*)(dyn + 32768);          // staged bids (until compaction)
    float* logit = (float*)(dyn + 32768);        // logits (after compaction)

    __shared__ __align__(16) float Ms[4096];     // 16 KB
    __shared__ __align__(16) float Ss[4096];     // 16 KB (S_prev staged)
    __shared__ __align__(16) float u[256];       // [QL | KL | VL | attn]
    __shared__ __align__(16) float qf[64], zs[64], errv[64], outlat[64];
    __shared__ __align__(16) float rh[128], gh[256], gout[192];
    __shared__ float partv[8][64];
    __shared__ float epartv[8][64];
    __shared__ float sarr[64];
    __shared__ float red[512];
    __shared__ __align__(16) float accv[32][64]; // 8 KB
    __shared__ int warpCnt[16];
    __shared__ int warpBase[17];
    __shared__ int s_i1, s_i2;
    __shared__ float s_max, s_sum;
    __shared__ float sc[8];
    __shared__ float smu[8], sinv[8];

    int bh = blockIdx.x;
    int b = bh >> 4, h = bh & 15;
    int tid = threadIdx.x;
    int warp = tid >> 5, lane = tid & 31;

    // ===== phase A: stage M, S_prev, z, bids (overlaps W stream below) =====
    {
        const float4* Mg4 = (const float4*)(M + (size_t)bh * 4096);
        const float4* Sg4 = (const float4*)(S_prev + (size_t)bh * 4096);
        float4* Ms4 = (float4*)Ms;
        float4* Ss4 = (float4*)Ss;
#pragma unroll
        for (int k = 0; k < 2; ++k) Ms4[tid + k * 512] = Mg4[tid + k * 512];
#pragma unroll
        for (int k = 0; k < 2; ++k) Ss4[tid + k * 512] = Sg4[tid + k * 512];
        const int4* br4 = (const int4*)(bids + b * W_TOT);
        int4* bs4 = (int4*)bidsS;
#pragma unroll
        for (int k = 0; k < 4; ++k) bs4[tid + k * 512] = br4[tid + k * 512];
        if (tid < 64) zs[tid] = z[bh * 64 + tid];
    }

    // ===== phase B: LN stats (warps 0-7, one batch each; x is L2-hot) =====
    if (warp < 8) {
        int bb = warp;
        const float4* xr = (const float4*)(x + bb * D_MODEL);
        float s = 0.0f, ss = 0.0f;
#pragma unroll
        for (int i = 0; i < 16; ++i) {
            float4 v = xr[i * 32 + lane];
            s  += v.x + v.y + v.z + v.w;
            ss += v.x * v.x + v.y * v.y + v.z * v.z + v.w * v.w;
        }
#pragma unroll
        for (int o = 16; o; o >>= 1) {
            s  += __shfl_down_sync(FULL, s, o);
            ss += __shfl_down_sync(FULL, ss, o);
        }
        if (lane == 0) {
            float mu = s * (1.0f / D_MODEL);
            float var = ss * (1.0f / D_MODEL) - mu * mu;
            smu[bb] = mu;
            sinv[bb] = rsqrtf(var + 1e-5f);
        }
    }
    __syncthreads();

    // ===== phase C: QKV GEMM — this block computes cols [bh*48, bh*48+48) =====
    {
        int colBase = bh * 48 + warp * 3;
        float acc[3][8];
#pragma unroll
        for (int c = 0; c < 3; c++)
#pragma unroll
            for (int bb = 0; bb < 8; bb++) acc[c][bb] = 0.0f;

        for (int tile = 0; tile < 4; ++tile) {
            int k0 = tile * 512;
#pragma unroll
            for (int i2 = 0; i2 < 2; ++i2) {
                int i = tid + i2 * 512;
                int bb = i >> 7, kk = i & 127;
                float4 xv = *(const float4*)&x[bb * D_MODEL + k0 + kk * 4];
                float4 gv = *(const float4*)&lg[k0 + kk * 4];
                float4 bv = *(const float4*)&lb[k0 + kk * 4];
                float mu = smu[bb], inv = sinv[bb];
                float4 hv;
                hv.x = (xv.x - mu) * inv * gv.x + bv.x;
                hv.y = (xv.y - mu) * inv * gv.y + bv.y;
                hv.z = (xv.z - mu) * inv * gv.z + bv.z;
                hv.w = (xv.w - mu) * inv * gv.w + bv.w;
                hs4[bb * 128 + kk] = hv;
            }
            __syncthreads();
#pragma unroll
            for (int kk = 0; kk < 4; ++kk) {
                int k4 = lane + kk * 32;
                float4 wv[3];
#pragma unroll
                for (int c = 0; c < 3; c++)
                    wv[c] = *(const float4*)(&W[(size_t)(colBase + c) * D_MODEL + k0 + k4 * 4]);
#pragma unroll
                for (int bb = 0; bb < 8; bb++) {
                    float4 hv = hs4[bb * 128 + k4];
#pragma unroll
                    for (int c = 0; c < 3; c++)
                        acc[c][bb] += wv[c].x * hv.x + wv[c].y * hv.y + wv[c].z * hv.z + wv[c].w * hv.w;
                }
            }
            __syncthreads();
        }
#pragma unroll
        for (int c = 0; c < 3; c++)
#pragma unroll
            for (int bb = 0; bb < 8; bb++) {
                float v = acc[c][bb];
#pragma unroll
                for (int o = 16; o; o >>= 1) v += __shfl_down_sync(FULL, v, o);
                if (lane == 0) g_qkv[bb * QKV_COLS + colBase + c] = v;
            }
    }
    __threadfence();
    __syncthreads();

    // ===== barrier 1: all 128 blocks (monotone ticket; no reset needed) =====
    if (tid == 0) {
        int t = atomicAdd(&g_cnt1, 1);
        int tgt = t - (t & 127) + 128;
        volatile int* vc = &g_cnt1;
        while (*vc < tgt) { }
        __threadfence();
    }
    __syncthreads();

    // ===== phase D: latent projections for own (b,h) =====
    if (tid < 384) {
        int o = tid >> 1, half = tid & 1;
        int which = o >> 6, r = o & 63;
        const float* vec = g_qkv + b * QKV_COLS + h * 384 + which * 128 + half * 64;
        const float* E = (which == 0 ? Eq : (which == 1 ? Ek : Ev))
                         + (size_t)h * 8192 + (half * 64) * 64 + r;
        float acc = 0.0f;
#pragma unroll 8
        for (int d = 0; d < 64; ++d) acc += vec[d] * E[d * 64];
        acc += __shfl_down_sync(FULL, acc, 1);
        if (half == 0) u[o] = acc;
    }
    __syncthreads();

    // ===== phase E: score partials for own head =====
    if (tid < 256) {
        int n = tid >> 2, q = tid & 3;
        const float4* mrow = (const float4*)&bm[(((size_t)n * B_SZ + b) * H_N + h) * 64];
        const float4* qv4 = (const float4*)u;
        float p = 0.0f;
#pragma unroll
        for (int j = 0; j < 4; ++j) {
            float4 mv = mrow[q * 4 + j], qv = qv4[q * 4 + j];
            p += mv.x * qv.x + mv.y * qv.y + mv.z * qv.z + mv.w * qv.w;
        }
        p += __shfl_down_sync(FULL, p, 2);
        p += __shfl_down_sync(FULL, p, 1);
        if (q == 0) g_part[(b * H_N + h) * NB + n] = p;
    }
    __threadfence();
    __syncthreads();

    // ===== barrier 2 ARRIVE (per batch) =====
    int tgt2 = 0;
    if (tid == 0) {
        int t = atomicAdd(&g_cntB[b], 1);
        tgt2 = t - (t & 15) + 16;
    }

    // ===== phase F: independent tail-prep while peers arrive =====
    if (tid < 64) qf[tid] = softplusf(u[tid]);
    __syncthreads();
    {
        int s = tid & 63, g = tid >> 6;
        float a = 0.0f, e = 0.0f;
        for (int r = g; r < 64; r += 8) {
            float mrs = Ms[r * 64 + s];
            a += qf[r] * mrs;
            e += u[64 + r] * mrs;
        }
        partv[g][s] = a;
        epartv[g][s] = e;
    }
    if (tid < 128) {
        const float4* wr = (const float4*)(r1w + tid * 64);
        const float4* qv = (const float4*)u;
        float a = r1b[tid];
#pragma unroll
        for (int k = 0; k < 16; ++k) {
            float4 wv = wr[k], uv = qv[k];
            a += wv.x * uv.x + wv.y * uv.y + wv.z * uv.z + wv.w * uv.w;
        }
        rh[tid] = geluf(a);
    }
    __syncthreads();

    // ===== barrier 2 WAIT =====
    if (tid == 0) {
        volatile int* vc = &g_cntB[b];
        while (*vc < tgt2) { }
        __threadfence();
    }
    __syncthreads();

    // ===== sum partials + decay (256 threads), top-2 =====
    if (tid < 256) {
        int n = tid >> 2, p = tid & 3;
        float s = 0.0f;
#pragma unroll
        for (int h2 = p; h2 < H_N; h2 += 4)
            s += g_part[(b * H_N + h2) * NB + n];
        s += __shfl_down_sync(FULL, s, 2);
        s += __shfl_down_sync(FULL, s, 1);
        if (p == 0)
            sarr[n] = s * exp2f((float)(63 - n) * LOG2_GAMMA) * 0.0078125f;
    }
    __syncthreads();
    if (tid < 32) {
        float v0 = sarr[tid], v1 = sarr[tid + 32];
        float bv; int bi;
        if (v0 >= v1) { bv = v0; bi = tid; } else { bv = v1; bi = tid + 32; }
#pragma unroll
        for (int o = 16; o; o >>= 1) {
            float ov = __shfl_down_sync(FULL, bv, o);
            int   oi = __shfl_down_sync(FULL, bi, o);
            if (ov > bv || (ov == bv && oi < bi)) { bv = ov; bi = oi; }
        }
        int i1 = __shfl_sync(FULL, bi, 0);
        float w0 = (tid == i1)      ? -INFINITY : v0;
        float w1 = (tid + 32 == i1) ? -INFINITY : v1;
        float cv; int ci;
        if (w0 >= w1) { cv = w0; ci = tid; } else { cv = w1; ci = tid + 32; }
#pragma unroll
        for (int o = 16; o; o >>= 1) {
            float ov = __shfl_down_sync(FULL, cv, o);
            int   oi = __shfl_down_sync(FULL, ci, o);
            if (ov > cv || (ov == cv && oi < ci)) { cv = ov; ci = oi; }
        }
        if (tid == 0) { s_i1 = i1; s_i2 = ci; }
    }
    __syncthreads();

    // ===== compaction from smem-staged bids =====
    int nw;
    {
        int i1 = s_i1, i2 = s_i2, cur = curp[0];
        const int4* bs4 = (const int4*)bidsS;
        unsigned mbits = 0;
        int c = 0;
#pragma unroll
        for (int k = 0; k < 4; ++k) {
            int4 v = bs4[tid * 4 + k];
            if (v.x == i1 || v.x == i2 || v.x == cur) { mbits |= 1u << (k * 4 + 0); c++; }
            if (v.y == i1 || v.y == i2 || v.y == cur) { mbits |= 1u << (k * 4 + 1); c++; }
            if (v.z == i1 || v.z == i2 || v.z == cur) { mbits |= 1u << (k * 4 + 2); c++; }
            if (v.w == i1 || v.w == i2 || v.w == cur) { mbits |= 1u << (k * 4 + 3); c++; }
        }
        int inc = c;
#pragma unroll
        for (int o = 1; o < 32; o <<= 1) {
            int t = __shfl_up_sync(FULL, inc, o);
            if (lane >= o) inc += t;
        }
        if (lane == 31) warpCnt[warp] = inc;
        __syncthreads();
        if (tid == 0) {
            int t = 0;
#pragma unroll
            for (int k = 0; k < 16; ++k) { warpBase[k] = t; t += warpCnt[k]; }
            warpBase[16] = t;
        }
        __syncthreads();
        int off = warpBase[warp] + (inc - c);
        int base = tid * 16;
#pragma unroll
        for (int j = 0; j < 16; ++j)
            if ((mbits >> j) & 1u) widx[off++] = base + j;
        nw = warpBase[16];
    }
    __syncthreads();

    // ===== attention =====
    {
        const float4* qr = (const float4*)u;
        float lm = -INFINITY;
        for (int i = tid; i < nw; i += 512) {
            int w = widx[i];
            const float4* kr = (const float4*)&Kl[((size_t)bh * W_TOT + w) * 64];
            float d = 0.0f;
#pragma unroll
            for (int r4 = 0; r4 < 16; ++r4) {
                float4 kv = kr[r4], qv = qr[r4];
                d += kv.x * qv.x + kv.y * qv.y + kv.z * qv.z + kv.w * qv.w;
            }
            d *= 0.125f;
            logit[i] = d;
            lm = fmaxf(lm, d);
        }
        red[tid] = lm; __syncthreads();
        for (int o = 256; o; o >>= 1) { if (tid < o) red[tid] = fmaxf(red[tid], red[tid + o]); __syncthreads(); }
        if (tid == 0) s_max = red[0];
        __syncthreads();

        float mx = s_max;
        float ls = 0.0f;
        for (int i = tid; i < nw; i += 512) {
            float e = expf(logit[i] - mx);
            logit[i] = e;
            ls += e;
        }
        red[tid] = ls; __syncthreads();
        for (int o = 256; o; o >>= 1) { if (tid < o) red[tid] += red[tid + o]; __syncthreads(); }
        if (tid == 0) s_sum = red[0];
        __syncthreads();

        int r4 = tid & 15, g = tid >> 4;
        float4 a4 = make_float4(0.0f, 0.0f, 0.0f, 0.0f);
        for (int i = g; i < nw; i += 32) {
            int w = widx[i];
            float pw = logit[i];
            float4 v = *(const float4*)&Vl[((size_t)bh * W_TOT + w) * 64 + r4 * 4];
            a4.x += pw * v.x; a4.y += pw * v.y; a4.z += pw * v.z; a4.w += pw * v.w;
        }
        *(float4*)&accv[g][r4 * 4] = a4;
        __syncthreads();
        if (tid < 64) {
            float a = 0.0f;
#pragma unroll
            for (int gg = 0; gg < 32; ++gg) a += accv[gg][tid];
            u[192 + tid] = a / s_sum;
        }
    }
    __syncthreads();

    // ===== gate MLP (needs attn) =====
    {
        int o = tid >> 1, half = tid & 1;
        const float4* wr = (const float4*)(g1w + (size_t)o * 256 + half * 128);
        const float4* uv4 = (const float4*)u + half * 32;
        float a = 0.0f;
#pragma unroll
        for (int k = 0; k < 32; ++k) {
            float4 wv = wr[k], uv = uv4[k];
            a += wv.x * uv.x + wv.y * uv.y + wv.z * uv.z + wv.w * uv.w;
        }
        a += __shfl_down_sync(FULL, a, 1);
        if (half == 0) gh[o] = geluf(a + g1b[o]);
    }
    __syncthreads();
    if (tid < 384) {
        int o = tid >> 1, half = tid & 1;
        const float4* wr = (const float4*)(g2w + (size_t)o * 256 + half * 128);
        const float4* gv4 = (const float4*)gh + half * 32;
        float a = 0.0f;
#pragma unroll
        for (int k = 0; k < 32; ++k) {
            float4 wv = wr[k], gv = gv4[k];
            a += wv.x * gv.x + wv.y * gv.y + wv.z * gv.z + wv.w * gv.w;
        }
        a += __shfl_down_sync(FULL, a, 1);
        if (half == 0) gout[o] = a + g2b[o];
    }
    __syncthreads();

    // ===== scalar reductions (warp-parallel) =====
    if (warp == 0) {
        float t = qf[lane] * zs[lane] + qf[lane + 32] * zs[lane + 32];
#pragma unroll
        for (int o = 16; o; o >>= 1) t += __shfl_down_sync(FULL, t, o);
        if (lane == 0) sc[0] = t + 1e-6f;
    } else if (warp == 1) {
        float t = 0.0f;
#pragma unroll
        for (int k = 0; k < 4; ++k) t += rh[lane + k * 32] * r2w[lane + k * 32];
#pragma unroll
        for (int o = 16; o; o >>= 1) t += __shfl_down_sync(FULL, t, o);
        if (lane == 0) sc[1] = sigmoidf(t + r2b[0]);
    } else if (warp == 2) {
        float t = gout[lane] + gout[lane + 32];
#pragma unroll
        for (int o = 16; o; o >>= 1) t += __shfl_down_sync(FULL, t, o);
        if (lane == 0) sc[2] = sigmoidf(t * (1.0f / 64.0f));
    } else if (warp == 3) {
        float t = gout[64 + lane] + gout[96 + lane];
#pragma unroll
        for (int o = 16; o; o >>= 1) t += __shfl_down_sync(FULL, t, o);
        if (lane == 0) sc[3] = softplusf(t * (1.0f / 64.0f));
    } else if (warp == 4) {
        float t = gout[128 + lane] + gout[160 + lane];
#pragma unroll
        for (int o = 16; o; o >>= 1) t += __shfl_down_sync(FULL, t, o);
        if (lane == 0) sc[4] = softplusf(t * (1.0f / 64.0f));
    }
    __syncthreads();

    // ===== lin, err, out_lat, z_new =====
    if (tid < 64) {
        float l = 0.0f, e = 0.0f;
#pragma unroll
        for (int g = 0; g < 8; ++g) { l += partv[g][tid]; e += epartv[g][tid]; }
        l /= sc[0];
        errv[tid] = e - u[128 + tid];
        float ps = sc[1];
        outlat[tid] = (1.0f - ps) * u[192 + tid] + ps * l;
        float zn = (1.0f - sc[2]) * zs[tid] + softplusf(u[64 + tid]);
        out[Z_OFF + bh * 64 + tid] = zn;
    }
    __syncthreads();

    // ===== state update (S from smem) + output projection =====
    {
        float eta = sc[3], theta = sc[4], oma = 1.0f - sc[2];
        float4* Mo4 = (float4*)(out + M_OFF + (size_t)bh * 4096);
        float4* So4 = (float4*)(out + S_OFF + (size_t)bh * 4096);
        const float4* ev4 = (const float4*)errv;
        const float4* Ms4 = (const float4*)Ms;
        const float4* Ss4 = (const float4*)Ss;
#pragma unroll
        for (int k = 0; k < 2; ++k) {
            int idx = tid + k * 512;
            int r = idx >> 4, s4 = idx & 15;
            float kl = u[64 + r];
            float4 e = ev4[s4];
            float4 sg = Ss4[idx];
            float4 ms = Ms4[idx];
            float4 sn;
            sn.x = eta * sg.x - theta * (kl * e.x);
            sn.y = eta * sg.y - theta * (kl * e.y);
            sn.z = eta * sg.z - theta * (kl * e.z);
            sn.w = eta * sg.w - theta * (kl * e.w);
            So4[idx] = sn;
            float4 mn;
            mn.x = oma * ms.x + sn.x;
            mn.y = oma * ms.y + sn.y;
            mn.z = oma * ms.z + sn.z;
            mn.w = oma * ms.w + sn.w;
            Mo4[idx] = mn;
        }
    }
    if (tid < 256) {
        int o = tid >> 1, half = tid & 1;
        const float4* er = (const float4*)(Ev + ((size_t)h * 128 + o) * 64) + half * 8;
        const float4* ov = (const float4*)outlat + half * 8;
        float a = 0.0f;
#pragma unroll
        for (int k = 0; k < 8; ++k) {
            float4 e = er[k], oo = ov[k];
            a += e.x * oo.x + e.y * oo.y + e.z * oo.z + e.w * oo.w;
        }
        a += __shfl_down_sync(FULL, a, 1);
        if (half == 0) out[OUT_OFF + b * 2048 + h * 128 + o] = a;
    }
}

// ============================================================
extern "C" void kernel_launch(void* const* d_in, const int* in_sizes, int n_in,
                              void* d_out, int out_size) {
    const float* x     = (const float*)d_in[0];
    const float* ln_g  = (const float*)d_in[1];
    const float* ln_b  = (const float*)d_in[2];
    const float* W_qkv = (const float*)d_in[3];
    const float* E_q   = (const float*)d_in[4];
    const float* E_k   = (const float*)d_in[5];
    const float* E_v   = (const float*)d_in[6];
    const float* K_lat = (const float*)d_in[7];
    const float* V_lat = (const float*)d_in[8];
    const float* bm    = (const float*)d_in[9];
    const float* M     = (const float*)d_in[10];
    const float* z     = (const float*)d_in[11];
    const float* S_prev= (const float*)d_in[12];
    const float* r1w   = (const float*)d_in[13];
    const float* r1b   = (const float*)d_in[14];
    const float* r2w   = (const float*)d_in[15];
    const float* r2b   = (const float*)d_in[16];
    const float* g1w   = (const float*)d_in[17];
    const float* g1b   = (const float*)d_in[18];
    const float* g2w   = (const float*)d_in[19];
    const float* g2b   = (const float*)d_in[20];
    const int*   bids  = (const int*)d_in[21];
    const int*   cur   = (const int*)d_in[22];
    float* out = (float*)d_out;

    static bool attr_done = false;
    if (!attr_done) {
        cudaFuncSetAttribute(k_all, cudaFuncAttributeMaxDynamicSharedMemorySize,
                             W_TOT * 8);
        attr_done = true;
    }

    k_all<<<B_SZ * H_N, 512, W_TOT * 8>>>(x, ln_g, ln_b, W_qkv,
                                          K_lat, V_lat, bm, bids, cur,
                                          E_q, E_k, E_v, M, z, S_prev,
                                          r1w, r1b, r2w, r2b,
                                          g1w, g1b, g2w, g2b, out);
}

// round 8
// speedup vs baseline: 2.1586x; 1.0437x over previous
#include <cuda_runtime.h>
#include <cuda_bf16.h>
#include <math.h>

#define B_SZ 8
#define D_MODEL 2048
#define H_N 16
#define R_DIM 64
#define W_TOT 8192
#define NB 64
#define QKV_COLS 6144

#define OUT_OFF 0
#define M_OFF   (B_SZ * H_N * 128)                       // 16384
#define Z_OFF   (M_OFF + B_SZ * H_N * R_DIM * R_DIM)     // 540672
#define S_OFF   (Z_OFF + B_SZ * H_N * R_DIM)             // 548864

#define LOG2_GAMMA (-0.043943347587597055f)
#define FULL 0xffffffffu

// -------- scratch (device globals; zero-init, monotone counters) --------
__device__ __align__(16) float g_qkv[B_SZ * QKV_COLS];
__device__ __align__(16) float g_part[B_SZ * H_N * NB];
__device__ int g_cnt1;
__device__ int g_cntB[B_SZ];

__device__ __forceinline__ float softplusf(float x) {
    return fmaxf(x, 0.0f) + log1pf(expf(-fabsf(x)));
}
__device__ __forceinline__ float geluf(float x) {
    return 0.5f * x * (1.0f + erff(x * 0.70710678118654752440f));
}
__device__ __forceinline__ float sigmoidf(float x) {
    return 1.0f / (1.0f + expf(-x));
}

// ============================================================
// ONE kernel, grid=128 (b,h), block=512, dyn smem 48KB
// dyn: [0,16K) GEMM h-tile   [16K,48K) staged bids
// ============================================================
__global__ void __launch_bounds__(512) k_all(
    const float* __restrict__ x, const float* __restrict__ lg,
    const float* __restrict__ lb, const float* __restrict__ W,
    const float* __restrict__ Kl, const float* __restrict__ Vl,
    const float* __restrict__ bm, const int* __restrict__ bids,
    const int* __restrict__ curp,
    const float* __restrict__ Eq, const float* __restrict__ Ek,
    const float* __restrict__ Ev,
    const float* __restrict__ M, const float* __restrict__ z,
    const float* __restrict__ S_prev,
    const float* __restrict__ r1w, const float* __restrict__ r1b,
    const float* __restrict__ r2w, const float* __restrict__ r2b,
    const float* __restrict__ g1w, const float* __restrict__ g1b,
    const float* __restrict__ g2w, const float* __restrict__ g2b,
    float* __restrict__ out) {

    extern __shared__ __align__(16) char dyn[];
    float4* hs4  = (float4*)dyn;                 // [1024] GEMM phase only
    int*   bidsS = (int*)(dyn + 16384);          // [8192]

    __shared__ __align__(16) float Ms[4096];     // 16 KB
    __shared__ __align__(16) float Ss[4096];     // 16 KB
    __shared__ __align__(16) float bmS[4096];    // 16 KB (own (b,h) bm slice)
    __shared__ __align__(16) float u[256];       // [QL | KL | VL | attn]
    __shared__ __align__(16) float qkvS[384];
    __shared__ __align__(16) float projTmp[384];
    __shared__ __align__(16) float qf[64], zs[64], errv[64], linp[64], outlat[64];
    __shared__ __align__(16) float rh[128], ghp[256], gout[192];
    __shared__ float partv[8][64];
    __shared__ float epartv[8][64];
    __shared__ float sarr[64];
    __shared__ float redw[16];
    __shared__ __align__(16) float accv[32][64]; // 8 KB
    __shared__ int widx[512];
    __shared__ float logit[512];
    __shared__ int warpCnt[16];
    __shared__ int warpBase[17];
    __shared__ int s_i1, s_i2;
    __shared__ float s_max, s_sum;
    __shared__ float sc[8];   // 0:qz 1:p_skip 2:alpha 3:eta 4:theta
    __shared__ float smu[8], sinv[8];

    int bh = blockIdx.x;
    int b = bh >> 4, h = bh & 15;
    int tid = threadIdx.x;
    int warp = tid >> 5, lane = tid & 31;

    // ===== phase A: stage M, S, bids, bm-slice, z (overlaps W stream) =====
    {
        const float4* Mg4 = (const float4*)(M + (size_t)bh * 4096);
        const float4* Sg4 = (const float4*)(S_prev + (size_t)bh * 4096);
        float4* Ms4 = (float4*)Ms;
        float4* Ss4 = (float4*)Ss;
#pragma unroll
        for (int k = 0; k < 2; ++k) Ms4[tid + k * 512] = Mg4[tid + k * 512];
#pragma unroll
        for (int k = 0; k < 2; ++k) Ss4[tid + k * 512] = Sg4[tid + k * 512];
        const int4* br4 = (const int4*)(bids + b * W_TOT);
        int4* bs4 = (int4*)bidsS;
#pragma unroll
        for (int k = 0; k < 4; ++k) bs4[tid + k * 512] = br4[tid + k * 512];
        // bm slice: row n (64 floats) from bm[((n*8+b)*16+h)*64]
        float4* bmS4 = (float4*)bmS;
#pragma unroll
        for (int k = 0; k < 2; ++k) {
            int i = tid + k * 512;          // 0..1023 float4s
            int n = i >> 4, c = i & 15;
            bmS4[i] = ((const float4*)&bm[(((size_t)n * B_SZ + b) * H_N + h) * 64])[c];
        }
        if (tid < 64) zs[tid] = z[bh * 64 + tid];
    }

    // ===== phase B: LN stats (warps 0-7) =====
    if (warp < 8) {
        int bb = warp;
        const float4* xr = (const float4*)(x + bb * D_MODEL);
        float s = 0.0f, ss = 0.0f;
#pragma unroll
        for (int i = 0; i < 16; ++i) {
            float4 v = xr[i * 32 + lane];
            s  += v.x + v.y + v.z + v.w;
            ss += v.x * v.x + v.y * v.y + v.z * v.z + v.w * v.w;
        }
#pragma unroll
        for (int o = 16; o; o >>= 1) {
            s  += __shfl_down_sync(FULL, s, o);
            ss += __shfl_down_sync(FULL, ss, o);
        }
        if (lane == 0) {
            float mu = s * (1.0f / D_MODEL);
            float var = ss * (1.0f / D_MODEL) - mu * mu;
            smu[bb] = mu;
            sinv[bb] = rsqrtf(var + 1e-5f);
        }
    }
    __syncthreads();

    // ===== phase C: QKV GEMM, cols [bh*48, bh*48+48), prefetched =====
    {
        int colBase = bh * 48 + warp * 3;
        float acc[3][8];
#pragma unroll
        for (int c = 0; c < 3; c++)
#pragma unroll
            for (int bb = 0; bb < 8; bb++) acc[c][bb] = 0.0f;

        for (int tile = 0; tile < 4; ++tile) {
            int k0 = tile * 512;
#pragma unroll
            for (int i2 = 0; i2 < 2; ++i2) {
                int i = tid + i2 * 512;
                int bb = i >> 7, kk = i & 127;
                float4 xv = *(const float4*)&x[bb * D_MODEL + k0 + kk * 4];
                float4 gv = *(const float4*)&lg[k0 + kk * 4];
                float4 bv = *(const float4*)&lb[k0 + kk * 4];
                float mu = smu[bb], inv = sinv[bb];
                float4 hv;
                hv.x = (xv.x - mu) * inv * gv.x + bv.x;
                hv.y = (xv.y - mu) * inv * gv.y + bv.y;
                hv.z = (xv.z - mu) * inv * gv.z + bv.z;
                hv.w = (xv.w - mu) * inv * gv.w + bv.w;
                hs4[bb * 128 + kk] = hv;
            }
            __syncthreads();

            const float* wp = W + (size_t)colBase * D_MODEL + k0 + lane * 4;
            float4 wcur[3], wnxt[3];
#pragma unroll
            for (int c = 0; c < 3; c++)
                wcur[c] = *(const float4*)(wp + (size_t)c * D_MODEL);
#pragma unroll
            for (int kk = 0; kk < 4; ++kk) {
                if (kk < 3) {
#pragma unroll
                    for (int c = 0; c < 3; c++)
                        wnxt[c] = *(const float4*)(wp + (size_t)c * D_MODEL + (kk + 1) * 128);
                }
                int k4 = lane + kk * 32;
#pragma unroll
                for (int bb = 0; bb < 8; bb++) {
                    float4 hv = hs4[bb * 128 + k4];
#pragma unroll
                    for (int c = 0; c < 3; c++)
                        acc[c][bb] += wcur[c].x * hv.x + wcur[c].y * hv.y
                                    + wcur[c].z * hv.z + wcur[c].w * hv.w;
                }
#pragma unroll
                for (int c = 0; c < 3; c++) wcur[c] = wnxt[c];
            }
            __syncthreads();
        }
#pragma unroll
        for (int c = 0; c < 3; c++)
#pragma unroll
            for (int bb = 0; bb < 8; bb++) {
                float v = acc[c][bb];
#pragma unroll
                for (int o = 16; o; o >>= 1) v += __shfl_down_sync(FULL, v, o);
                if (lane == 0) g_qkv[bb * QKV_COLS + colBase + c] = v;
            }
    }
    __threadfence();
    __syncthreads();

    // ===== barrier 1: all 128 blocks =====
    if (tid == 0) {
        int t = atomicAdd(&g_cnt1, 1);
        int tgt = t - (t & 127) + 128;
        volatile int* vc = &g_cnt1;
        while (*vc < tgt) { }
        __threadfence();
    }
    __syncthreads();

    // ===== phase D: stage qkv slice, coalesced projection =====
    if (tid < 384) qkvS[tid] = g_qkv[b * QKV_COLS + h * 384 + tid];
    __syncthreads();
    if (tid < 384) {
        int half = tid >= 192;
        int o = tid - half * 192;           // 0..191
        int which = o >> 6, r = o & 63;
        const float* E = (which == 0 ? Eq : (which == 1 ? Ek : Ev))
                         + (size_t)h * 8192 + half * 64 * 64 + r;
        const float* vec = qkvS + which * 128 + half * 64;
        float acc = 0.0f;
#pragma unroll 16
        for (int d = 0; d < 64; ++d) acc += vec[d] * E[d * 64];
        projTmp[tid] = acc;
    }
    __syncthreads();
    if (tid < 192) u[tid] = projTmp[tid] + projTmp[tid + 192];
    __syncthreads();

    // ===== phase E: score partials from smem bm =====
    if (tid < 256) {
        int n = tid >> 2, q = tid & 3;
        const float4* mrow = (const float4*)(bmS + n * 64);
        const float4* qv4 = (const float4*)u;
        float p = 0.0f;
#pragma unroll
        for (int j = 0; j < 4; ++j) {
            float4 mv = mrow[q * 4 + j], qv = qv4[q * 4 + j];
            p += mv.x * qv.x + mv.y * qv.y + mv.z * qv.z + mv.w * qv.w;
        }
        p += __shfl_down_sync(FULL, p, 2);
        p += __shfl_down_sync(FULL, p, 1);
        if (q == 0) g_part[(b * H_N + h) * NB + n] = p;
    }
    __threadfence();
    __syncthreads();

    // ===== barrier 2 ARRIVE =====
    int tgt2 = 0;
    if (tid == 0) {
        int t = atomicAdd(&g_cntB[b], 1);
        tgt2 = t - (t & 15) + 16;
    }

    // ===== pre-attention work while peers arrive =====
    // P1: gh_pre = g1b + g1w[:, 0:192] @ u[0:192]   (all 512 threads)
    {
        int o = tid >> 1, half = tid & 1;
        const float4* wr = (const float4*)(g1w + (size_t)o * 256 + half * 96);
        const float4* uv4 = (const float4*)u + half * 24;
        float a = 0.0f;
#pragma unroll
        for (int k = 0; k < 24; ++k) {
            float4 wv = wr[k], uv = uv4[k];
            a += wv.x * uv.x + wv.y * uv.y + wv.z * uv.z + wv.w * uv.w;
        }
        a += __shfl_down_sync(FULL, a, 1);
        if (half == 0) ghp[o] = a + g1b[o];
    }
    // P2: qf + rh (disjoint threads, both only need u)
    if (tid < 64) qf[tid] = softplusf(u[tid]);
    if (tid >= 256 && tid < 384) {
        int o = tid - 256;
        const float4* wr = (const float4*)(r1w + o * 64);
        const float4* qv = (const float4*)u;
        float a = r1b[o];
#pragma unroll
        for (int k = 0; k < 16; ++k) {
            float4 wv = wr[k], uv = qv[k];
            a += wv.x * uv.x + wv.y * uv.y + wv.z * uv.z + wv.w * uv.w;
        }
        rh[o] = geluf(a);
    }
    __syncthreads();
    // P3: lin/err partials over Ms (all threads)
    {
        int s = tid & 63, g = tid >> 6;
        float a = 0.0f, e = 0.0f;
        for (int r = g; r < 64; r += 8) {
            float mrs = Ms[r * 64 + s];
            a += qf[r] * mrs;
            e += u[64 + r] * mrs;
        }
        partv[g][s] = a;
        epartv[g][s] = e;
    }
    __syncthreads();
    // P4: qz (warp0), p_skip (warp1), errv/linp (warps 2-3)
    if (warp == 0) {
        float t = qf[lane] * zs[lane] + qf[lane + 32] * zs[lane + 32];
#pragma unroll
        for (int o = 16; o; o >>= 1) t += __shfl_down_sync(FULL, t, o);
        if (lane == 0) sc[0] = t + 1e-6f;
    } else if (warp == 1) {
        float t = 0.0f;
#pragma unroll
        for (int k = 0; k < 4; ++k) t += rh[lane + k * 32] * r2w[lane + k * 32];
#pragma unroll
        for (int o = 16; o; o >>= 1) t += __shfl_down_sync(FULL, t, o);
        if (lane == 0) sc[1] = sigmoidf(t + r2b[0]);
    } else if (warp == 2 || warp == 3) {
        int s = (warp - 2) * 32 + lane;
        float a = 0.0f, e = 0.0f;
#pragma unroll
        for (int g = 0; g < 8; ++g) { a += partv[g][s]; e += epartv[g][s]; }
        linp[s] = a;
        errv[s] = e - u[128 + s];
    }
    __syncthreads();

    // ===== barrier 2 WAIT =====
    if (tid == 0) {
        volatile int* vc = &g_cntB[b];
        while (*vc < tgt2) { }
        __threadfence();
    }
    __syncthreads();

    // ===== score sum + decay, top-2 =====
    if (tid < 256) {
        int n = tid >> 2, p = tid & 3;
        float s = 0.0f;
#pragma unroll
        for (int h2 = p; h2 < H_N; h2 += 4)
            s += g_part[(b * H_N + h2) * NB + n];
        s += __shfl_down_sync(FULL, s, 2);
        s += __shfl_down_sync(FULL, s, 1);
        if (p == 0)
            sarr[n] = s * exp2f((float)(63 - n) * LOG2_GAMMA) * 0.0078125f;
    }
    __syncthreads();
    if (tid < 32) {
        float v0 = sarr[tid], v1 = sarr[tid + 32];
        float bv; int bi;
        if (v0 >= v1) { bv = v0; bi = tid; } else { bv = v1; bi = tid + 32; }
#pragma unroll
        for (int o = 16; o; o >>= 1) {
            float ov = __shfl_down_sync(FULL, bv, o);
            int   oi = __shfl_down_sync(FULL, bi, o);
            if (ov > bv || (ov == bv && oi < bi)) { bv = ov; bi = oi; }
        }
        int i1 = __shfl_sync(FULL, bi, 0);
        float w0 = (tid == i1)      ? -INFINITY : v0;
        float w1 = (tid + 32 == i1) ? -INFINITY : v1;
        float cv; int ci;
        if (w0 >= w1) { cv = w0; ci = tid; } else { cv = w1; ci = tid + 32; }
#pragma unroll
        for (int o = 16; o; o >>= 1) {
            float ov = __shfl_down_sync(FULL, cv, o);
            int   oi = __shfl_down_sync(FULL, ci, o);
            if (ov > cv || (ov == cv && oi < ci)) { cv = ov; ci = oi; }
        }
        if (tid == 0) { s_i1 = i1; s_i2 = ci; }
    }
    __syncthreads();

    // ===== compaction (smem bids -> widx) =====
    int nw;
    {
        int i1 = s_i1, i2 = s_i2, cur = curp[0];
        const int4* bs4 = (const int4*)bidsS;
        unsigned mbits = 0;
        int c = 0;
#pragma unroll
        for (int k = 0; k < 4; ++k) {
            int4 v = bs4[tid * 4 + k];
            if (v.x == i1 || v.x == i2 || v.x == cur) { mbits |= 1u << (k * 4 + 0); c++; }
            if (v.y == i1 || v.y == i2 || v.y == cur) { mbits |= 1u << (k * 4 + 1); c++; }
            if (v.z == i1 || v.z == i2 || v.z == cur) { mbits |= 1u << (k * 4 + 2); c++; }
            if (v.w == i1 || v.w == i2 || v.w == cur) { mbits |= 1u << (k * 4 + 3); c++; }
        }
        int inc = c;
#pragma unroll
        for (int o = 1; o < 32; o <<= 1) {
            int t = __shfl_up_sync(FULL, inc, o);
            if (lane >= o) inc += t;
        }
        if (lane == 31) warpCnt[warp] = inc;
        __syncthreads();
        if (tid == 0) {
            int t = 0;
#pragma unroll
            for (int k = 0; k < 16; ++k) { warpBase[k] = t; t += warpCnt[k]; }
            warpBase[16] = t;
        }
        __syncthreads();
        int off = warpBase[warp] + (inc - c);
        int base = tid * 16;
#pragma unroll
        for (int j = 0; j < 16; ++j)
            if ((mbits >> j) & 1u) widx[off++] = base + j;
        nw = warpBase[16];
    }
    __syncthreads();

    // ===== attention =====
    {
        const float4* qr = (const float4*)u;
        float lm = -INFINITY;
        for (int i = tid; i < nw; i += 512) {
            int w = widx[i];
            const float4* kr = (const float4*)&Kl[((size_t)bh * W_TOT + w) * 64];
            float d = 0.0f;
#pragma unroll
            for (int r4 = 0; r4 < 16; ++r4) {
                float4 kv = kr[r4], qv = qr[r4];
                d += kv.x * qv.x + kv.y * qv.y + kv.z * qv.z + kv.w * qv.w;
            }
            d *= 0.125f;
            logit[i] = d;
            lm = fmaxf(lm, d);
        }
#pragma unroll
        for (int o = 16; o; o >>= 1) lm = fmaxf(lm, __shfl_down_sync(FULL, lm, o));
        if (lane == 0) redw[warp] = lm;
        __syncthreads();
        if (warp == 0) {
            float m = (lane < 16) ? redw[lane] : -INFINITY;
#pragma unroll
            for (int o = 16; o; o >>= 1) m = fmaxf(m, __shfl_down_sync(FULL, m, o));
            if (lane == 0) s_max = m;
        }
        __syncthreads();

        float mx = s_max;
        float ls = 0.0f;
        for (int i = tid; i < nw; i += 512) {
            float e = expf(logit[i] - mx);
            logit[i] = e;
            ls += e;
        }
#pragma unroll
        for (int o = 16; o; o >>= 1) ls += __shfl_down_sync(FULL, ls, o);
        if (lane == 0) redw[warp] = ls;
        __syncthreads();
        if (warp == 0) {
            float m = (lane < 16) ? redw[lane] : 0.0f;
#pragma unroll
            for (int o = 16; o; o >>= 1) m += __shfl_down_sync(FULL, m, o);
            if (lane == 0) s_sum = m;
        }
        __syncthreads();

        int r4 = tid & 15, g = tid >> 4;
        float4 a4 = make_float4(0.0f, 0.0f, 0.0f, 0.0f);
        for (int i = g; i < nw; i += 32) {
            int w = widx[i];
            float pw = logit[i];
            float4 v = *(const float4*)&Vl[((size_t)bh * W_TOT + w) * 64 + r4 * 4];
            a4.x += pw * v.x; a4.y += pw * v.y; a4.z += pw * v.z; a4.w += pw * v.w;
        }
        *(float4*)&accv[g][r4 * 4] = a4;
        __syncthreads();
        if (tid < 64) {
            float a = 0.0f;
#pragma unroll
            for (int gg = 0; gg < 32; ++gg) a += accv[gg][tid];
            u[192 + tid] = a / s_sum;
        }
    }
    __syncthreads();

    // ===== gh fix-up: gh = gelu(gh_pre + g1w[:,192:256] @ attn) =====
    {
        int o = tid >> 1, half = tid & 1;
        const float4* wr = (const float4*)(g1w + (size_t)o * 256 + 192 + half * 32);
        const float4* uv4 = (const float4*)(u + 192) + half * 8;
        float a = 0.0f;
#pragma unroll
        for (int k = 0; k < 8; ++k) {
            float4 wv = wr[k], uv = uv4[k];
            a += wv.x * uv.x + wv.y * uv.y + wv.z * uv.z + wv.w * uv.w;
        }
        a += __shfl_down_sync(FULL, a, 1);
        if (half == 0) ghp[o] = geluf(ghp[o] + a);
    }
    __syncthreads();

    // ===== gout = g2b + g2w @ gh =====
    if (tid < 384) {
        int o = tid >> 1, half = tid & 1;
        const float4* wr = (const float4*)(g2w + (size_t)o * 256 + half * 128);
        const float4* gv4 = (const float4*)ghp + half * 32;
        float a = 0.0f;
#pragma unroll
        for (int k = 0; k < 32; ++k) {
            float4 wv = wr[k], gv = gv4[k];
            a += wv.x * gv.x + wv.y * gv.y + wv.z * gv.z + wv.w * gv.w;
        }
        a += __shfl_down_sync(FULL, a, 1);
        if (half == 0) gout[o] = a + g2b[o];
    }
    __syncthreads();

    // ===== alpha/eta/theta (warps 0-2) =====
    if (warp == 0) {
        float t = gout[lane] + gout[lane + 32];
#pragma unroll
        for (int o = 16; o; o >>= 1) t += __shfl_down_sync(FULL, t, o);
        if (lane == 0) sc[2] = sigmoidf(t * (1.0f / 64.0f));
    } else if (warp == 1) {
        float t = gout[64 + lane] + gout[96 + lane];
#pragma unroll
        for (int o = 16; o; o >>= 1) t += __shfl_down_sync(FULL, t, o);
        if (lane == 0) sc[3] = softplusf(t * (1.0f / 64.0f));
    } else if (warp == 2) {
        float t = gout[128 + lane] + gout[160 + lane];
#pragma unroll
        for (int o = 16; o; o >>= 1) t += __shfl_down_sync(FULL, t, o);
        if (lane == 0) sc[4] = softplusf(t * (1.0f / 64.0f));
    }
    __syncthreads();

    // ===== out_lat, z_new =====
    if (tid < 64) {
        float l = linp[tid] / sc[0];
        float ps = sc[1];
        outlat[tid] = (1.0f - ps) * u[192 + tid] + ps * l;
        float zn = (1.0f - sc[2]) * zs[tid] + softplusf(u[64 + tid]);
        out[Z_OFF + bh * 64 + tid] = zn;
    }
    __syncthreads();

    // ===== state update + output projection =====
    {
        float eta = sc[3], theta = sc[4], oma = 1.0f - sc[2];
        float4* Mo4 = (float4*)(out + M_OFF + (size_t)bh * 4096);
        float4* So4 = (float4*)(out + S_OFF + (size_t)bh * 4096);
        const float4* ev4 = (const float4*)errv;
        const float4* Ms4 = (const float4*)Ms;
        const float4* Ss4 = (const float4*)Ss;
#pragma unroll
        for (int k = 0; k < 2; ++k) {
            int idx = tid + k * 512;
            int r = idx >> 4, s4 = idx & 15;
            float kl = u[64 + r];
            float4 e = ev4[s4];
            float4 sg = Ss4[idx];
            float4 ms = Ms4[idx];
            float4 sn;
            sn.x = eta * sg.x - theta * (kl * e.x);
            sn.y = eta * sg.y - theta * (kl * e.y);
            sn.z = eta * sg.z - theta * (kl * e.z);
            sn.w = eta * sg.w - theta * (kl * e.w);
            So4[idx] = sn;
            float4 mn;
            mn.x = oma * ms.x + sn.x;
            mn.y = oma * ms.y + sn.y;
            mn.z = oma * ms.z + sn.z;
            mn.w = oma * ms.w + sn.w;
            Mo4[idx] = mn;
        }
    }
    if (tid < 256) {
        int o = tid >> 1, half = tid & 1;
        const float4* er = (const float4*)(Ev + ((size_t)h * 128 + o) * 64) + half * 8;
        const float4* ov = (const float4*)outlat + half * 8;
        float a = 0.0f;
#pragma unroll
        for (int k = 0; k < 8; ++k) {
            float4 e = er[k], oo = ov[k];
            a += e.x * oo.x + e.y * oo.y + e.z * oo.z + e.w * oo.w;
        }
        a += __shfl_down_sync(FULL, a, 1);
        if (half == 0) out[OUT_OFF + b * 2048 + h * 128 + o] = a;
    }
}

// ============================================================
extern "C" void kernel_launch(void* const* d_in, const int* in_sizes, int n_in,
                              void* d_out, int out_size) {
    const float* x     = (const float*)d_in[0];
    const float* ln_g  = (const float*)d_in[1];
    const float* ln_b  = (const float*)d_in[2];
    const float* W_qkv = (const float*)d_in[3];
    const float* E_q   = (const float*)d_in[4];
    const float* E_k   = (const float*)d_in[5];
    const float* E_v   = (const float*)d_in[6];
    const float* K_lat = (const float*)d_in[7];
    const float* V_lat = (const float*)d_in[8];
    const float* bm    = (const float*)d_in[9];
    const float* M     = (const float*)d_in[10];
    const float* z     = (const float*)d_in[11];
    const float* S_prev= (const float*)d_in[12];
    const float* r1w   = (const float*)d_in[13];
    const float* r1b   = (const float*)d_in[14];
    const float* r2w   = (const float*)d_in[15];
    const float* r2b   = (const float*)d_in[16];
    const float* g1w   = (const float*)d_in[17];
    const float* g1b   = (const float*)d_in[18];
    const float* g2w   = (const float*)d_in[19];
    const float* g2b   = (const float*)d_in[20];
    const int*   bids  = (const int*)d_in[21];
    const int*   cur   = (const int*)d_in[22];
    float* out = (float*)d_out;

    static bool attr_done = false;
    if (!attr_done) {
        cudaFuncSetAttribute(k_all, cudaFuncAttributeMaxDynamicSharedMemorySize,
                             49152);
        attr_done = true;
    }

    k_all<<<B_SZ * H_N, 512, 49152>>>(x, ln_g, ln_b, W_qkv,
                                      K_lat, V_lat, bm, bids, cur,
                                      E_q, E_k, E_v, M, z, S_prev,
                                      r1w, r1b, r2w, r2b,
                                      g1w, g1b, g2w, g2b, out);
}

// round 9
// speedup vs baseline: 2.4127x; 1.1177x over previous
#include <cuda_runtime.h>
#include <cuda_bf16.h>
#include <math.h>

#define B_SZ 8
#define D_MODEL 2048
#define H_N 16
#define R_DIM 64
#define W_TOT 8192
#define NB 64
#define QKV_COLS 6144

#define OUT_OFF 0
#define M_OFF   (B_SZ * H_N * 128)                       // 16384
#define Z_OFF   (M_OFF + B_SZ * H_N * R_DIM * R_DIM)     // 540672
#define S_OFF   (Z_OFF + B_SZ * H_N * R_DIM)             // 548864

#define LOG2_GAMMA (-0.043943347587597055f)
#define FULL 0xffffffffu

// -------- scratch (device globals; zero-init, monotone counters) --------
__device__ __align__(16) float g_qkv[B_SZ * QKV_COLS];
__device__ __align__(16) float g_part[B_SZ * H_N * NB];
__device__ __align__(16) float g_mrow[B_SZ * 3 * 256];   // per-batch mean rows of g2w
__device__ float g_mb[B_SZ * 3];                          // per-batch mean biases
__device__ int g_grp[16];       // producer-group barrier counters (monotone)
__device__ int g_cntB[B_SZ];    // per-batch barrier counters (monotone)

__device__ __forceinline__ float softplusf(float x) {
    return fmaxf(x, 0.0f) + log1pf(expf(-fabsf(x)));
}
__device__ __forceinline__ float geluf(float x) {
    return 0.5f * x * (1.0f + erff(x * 0.70710678118654752440f));
}
__device__ __forceinline__ float sigmoidf(float x) {
    return 1.0f / (1.0f + expf(-x));
}

// ============================================================
// ONE kernel, grid=128 (b,h), block=512, dyn smem 48KB
// dyn: [0,16K) GEMM h-tile   [16K,48K) staged bids
// ============================================================
__global__ void __launch_bounds__(512) k_all(
    const float* __restrict__ x, const float* __restrict__ lg,
    const float* __restrict__ lb, const float* __restrict__ W,
    const float* __restrict__ Kl, const float* __restrict__ Vl,
    const float* __restrict__ bm, const int* __restrict__ bids,
    const int* __restrict__ curp,
    const float* __restrict__ Eq, const float* __restrict__ Ek,
    const float* __restrict__ Ev,
    const float* __restrict__ M, const float* __restrict__ z,
    const float* __restrict__ S_prev,
    const float* __restrict__ r1w, const float* __restrict__ r1b,
    const float* __restrict__ r2w, const float* __restrict__ r2b,
    const float* __restrict__ g1w, const float* __restrict__ g1b,
    const float* __restrict__ g2w, const float* __restrict__ g2b,
    float* __restrict__ out) {

    extern __shared__ __align__(16) char dyn[];
    float4* hs4  = (float4*)dyn;                 // [1024] GEMM phase only
    int*   bidsS = (int*)(dyn + 16384);          // [8192]

    __shared__ __align__(16) float Ms[4096];     // 16 KB
    __shared__ __align__(16) float Ss[4096];     // 16 KB
    __shared__ __align__(16) float bmS[4096];    // 16 KB (own (b,h) bm slice)
    __shared__ __align__(16) float u[256];       // [QL | KL | VL | attn]
    __shared__ __align__(16) float qkvS[384];
    __shared__ __align__(16) float projTmp[384];
    __shared__ __align__(16) float qf[64], zs[64], errv[64], linp[64], outlat[64];
    __shared__ __align__(16) float rh[128], ghp[256];
    __shared__ float partv[8][64];
    __shared__ float epartv[8][64];
    __shared__ float sarr[64];
    __shared__ float redw[16];
    __shared__ __align__(16) float accv[32][64]; // 8 KB (also scratch for mean-rows)
    __shared__ int widx[512];
    __shared__ float logit[512];
    __shared__ int warpCnt[16];
    __shared__ int warpBase[17];
    __shared__ int s_i1, s_i2;
    __shared__ float s_max, s_sum;
    __shared__ float sc[8];   // 0:qz 1:p_skip 2:alpha 3:eta 4:theta
    __shared__ float smu[8], sinv[8];

    int bh = blockIdx.x;
    int b = bh >> 4, h = bh & 15;
    int tid = threadIdx.x;
    int warp = tid >> 5, lane = tid & 31;

    // ===== phase A: stage M, S, bids, bm-slice, z (overlaps W stream) =====
    {
        const float4* Mg4 = (const float4*)(M + (size_t)bh * 4096);
        const float4* Sg4 = (const float4*)(S_prev + (size_t)bh * 4096);
        float4* Ms4 = (float4*)Ms;
        float4* Ss4 = (float4*)Ss;
#pragma unroll
        for (int k = 0; k < 2; ++k) Ms4[tid + k * 512] = Mg4[tid + k * 512];
#pragma unroll
        for (int k = 0; k < 2; ++k) Ss4[tid + k * 512] = Sg4[tid + k * 512];
        const int4* br4 = (const int4*)(bids + b * W_TOT);
        int4* bs4 = (int4*)bidsS;
#pragma unroll
        for (int k = 0; k < 4; ++k) bs4[tid + k * 512] = br4[tid + k * 512];
        float4* bmS4 = (float4*)bmS;
#pragma unroll
        for (int k = 0; k < 2; ++k) {
            int i = tid + k * 512;
            int n = i >> 4, c = i & 15;
            bmS4[i] = ((const float4*)&bm[(((size_t)n * B_SZ + b) * H_N + h) * 64])[c];
        }
        if (tid < 64) zs[tid] = z[bh * 64 + tid];
    }

    // ===== phase B: LN stats (warps 0-7) =====
    if (warp < 8) {
        int bb = warp;
        const float4* xr = (const float4*)(x + bb * D_MODEL);
        float s = 0.0f, ss = 0.0f;
#pragma unroll
        for (int i = 0; i < 16; ++i) {
            float4 v = xr[i * 32 + lane];
            s  += v.x + v.y + v.z + v.w;
            ss += v.x * v.x + v.y * v.y + v.z * v.z + v.w * v.w;
        }
#pragma unroll
        for (int o = 16; o; o >>= 1) {
            s  += __shfl_down_sync(FULL, s, o);
            ss += __shfl_down_sync(FULL, ss, o);
        }
        if (lane == 0) {
            float mu = s * (1.0f / D_MODEL);
            float var = ss * (1.0f / D_MODEL) - mu * mu;
            smu[bb] = mu;
            sinv[bb] = rsqrtf(var + 1e-5f);
        }
    }
    __syncthreads();

    // ===== phase C: QKV GEMM, cols [bh*48, bh*48+48), prefetched =====
    {
        int colBase = bh * 48 + warp * 3;
        float acc[3][8];
#pragma unroll
        for (int c = 0; c < 3; c++)
#pragma unroll
            for (int bb = 0; bb < 8; bb++) acc[c][bb] = 0.0f;

        for (int tile = 0; tile < 4; ++tile) {
            int k0 = tile * 512;
#pragma unroll
            for (int i2 = 0; i2 < 2; ++i2) {
                int i = tid + i2 * 512;
                int bb = i >> 7, kk = i & 127;
                float4 xv = *(const float4*)&x[bb * D_MODEL + k0 + kk * 4];
                float4 gv = *(const float4*)&lg[k0 + kk * 4];
                float4 bv = *(const float4*)&lb[k0 + kk * 4];
                float mu = smu[bb], inv = sinv[bb];
                float4 hv;
                hv.x = (xv.x - mu) * inv * gv.x + bv.x;
                hv.y = (xv.y - mu) * inv * gv.y + bv.y;
                hv.z = (xv.z - mu) * inv * gv.z + bv.z;
                hv.w = (xv.w - mu) * inv * gv.w + bv.w;
                hs4[bb * 128 + kk] = hv;
            }
            __syncthreads();

            const float* wp = W + (size_t)colBase * D_MODEL + k0 + lane * 4;
            float4 wcur[3], wnxt[3];
#pragma unroll
            for (int c = 0; c < 3; c++)
                wcur[c] = *(const float4*)(wp + (size_t)c * D_MODEL);
#pragma unroll
            for (int kk = 0; kk < 4; ++kk) {
                if (kk < 3) {
#pragma unroll
                    for (int c = 0; c < 3; c++)
                        wnxt[c] = *(const float4*)(wp + (size_t)c * D_MODEL + (kk + 1) * 128);
                }
                int k4 = lane + kk * 32;
#pragma unroll
                for (int bb = 0; bb < 8; bb++) {
                    float4 hv = hs4[bb * 128 + k4];
#pragma unroll
                    for (int c = 0; c < 3; c++)
                        acc[c][bb] += wcur[c].x * hv.x + wcur[c].y * hv.y
                                    + wcur[c].z * hv.z + wcur[c].w * hv.w;
                }
#pragma unroll
                for (int c = 0; c < 3; c++) wcur[c] = wnxt[c];
            }
            __syncthreads();
        }
#pragma unroll
        for (int c = 0; c < 3; c++)
#pragma unroll
            for (int bb = 0; bb < 8; bb++) {
                float v = acc[c][bb];
#pragma unroll
                for (int o = 16; o; o >>= 1) v += __shfl_down_sync(FULL, v, o);
                if (lane == 0) g_qkv[bb * QKV_COLS + colBase + c] = v;
            }
    }
    __threadfence();
    __syncthreads();

    // ===== barrier 1 (GROUPED): arrive at own producer group, wait on
    // group h (the 8 blocks producing cols [384h, 384h+384)).
    // All groups advance exactly 8 per launch; epoch from own ticket. =====
    if (tid == 0) {
        int t = atomicAdd(&g_grp[bh >> 3], 1);
        int tgt = ((t >> 3) + 1) * 8;
        volatile int* vc = &g_grp[h];
        while (*vc < tgt) { }
        __threadfence();
    }
    __syncthreads();

    // ===== phase D: stage qkv slice, coalesced projection =====
    if (tid < 384) qkvS[tid] = g_qkv[b * QKV_COLS + h * 384 + tid];
    __syncthreads();
    if (tid < 384) {
        int half = tid >= 192;
        int o = tid - half * 192;
        int which = o >> 6, r = o & 63;
        const float* E = (which == 0 ? Eq : (which == 1 ? Ek : Ev))
                         + (size_t)h * 8192 + half * 64 * 64 + r;
        const float* vec = qkvS + which * 128 + half * 64;
        float acc = 0.0f;
#pragma unroll 16
        for (int d = 0; d < 64; ++d) acc += vec[d] * E[d * 64];
        projTmp[tid] = acc;
    }
    __syncthreads();
    if (tid < 192) u[tid] = projTmp[tid] + projTmp[tid + 192];
    __syncthreads();

    // ===== phase E: score partials from smem bm =====
    if (tid < 256) {
        int n = tid >> 2, q = tid & 3;
        const float4* mrow = (const float4*)(bmS + n * 64);
        const float4* qv4 = (const float4*)u;
        float p = 0.0f;
#pragma unroll
        for (int j = 0; j < 4; ++j) {
            float4 mv = mrow[q * 4 + j], qv = qv4[q * 4 + j];
            p += mv.x * qv.x + mv.y * qv.y + mv.z * qv.z + mv.w * qv.w;
        }
        p += __shfl_down_sync(FULL, p, 2);
        p += __shfl_down_sync(FULL, p, 1);
        if (q == 0) g_part[(b * H_N + h) * NB + n] = p;
    }
    __threadfence();
    __syncthreads();

    // ===== mean-rows of g2w (blocks h<3 only; consumed after barrier-2) =====
    if (h < 3) {
        float* tmp = (float*)accv;   // scratch 512 floats
        int c = tid & 255, halfr = tid >> 8;
        const float* g2 = g2w + (size_t)(h * 64 + halfr * 32) * 256 + c;
        float s = 0.0f;
#pragma unroll
        for (int r = 0; r < 32; ++r) s += g2[r * 256];
        tmp[halfr * 256 + c] = s;
        __syncthreads();
        if (tid < 256)
            g_mrow[(b * 3 + h) * 256 + tid] = (tmp[tid] + tmp[256 + tid]) * (1.0f / 64.0f);
        if (tid == 256) {
            float t = 0.0f;
#pragma unroll
            for (int k = 0; k < 64; ++k) t += g2b[h * 64 + k];
            g_mb[b * 3 + h] = t * (1.0f / 64.0f);
        }
        __threadfence();
        __syncthreads();
    }

    // ===== barrier 2 ARRIVE =====
    int tgt2 = 0;
    if (tid == 0) {
        int t = atomicAdd(&g_cntB[b], 1);
        tgt2 = t - (t & 15) + 16;
    }

    // ===== pre-attention work while peers arrive =====
    // P1: gh_pre = g1b + g1w[:, 0:192] @ u[0:192]
    {
        int o = tid >> 1, half = tid & 1;
        const float4* wr = (const float4*)(g1w + (size_t)o * 256 + half * 96);
        const float4* uv4 = (const float4*)u + half * 24;
        float a = 0.0f;
#pragma unroll
        for (int k = 0; k < 24; ++k) {
            float4 wv = wr[k], uv = uv4[k];
            a += wv.x * uv.x + wv.y * uv.y + wv.z * uv.z + wv.w * uv.w;
        }
        a += __shfl_down_sync(FULL, a, 1);
        if (half == 0) ghp[o] = a + g1b[o];
    }
    if (tid < 64) qf[tid] = softplusf(u[tid]);
    if (tid >= 256 && tid < 384) {
        int o = tid - 256;
        const float4* wr = (const float4*)(r1w + o * 64);
        const float4* qv = (const float4*)u;
        float a = r1b[o];
#pragma unroll
        for (int k = 0; k < 16; ++k) {
            float4 wv = wr[k], uv = qv[k];
            a += wv.x * uv.x + wv.y * uv.y + wv.z * uv.z + wv.w * uv.w;
        }
        rh[o] = geluf(a);
    }
    __syncthreads();
    {
        int s = tid & 63, g = tid >> 6;
        float a = 0.0f, e = 0.0f;
        for (int r = g; r < 64; r += 8) {
            float mrs = Ms[r * 64 + s];
            a += qf[r] * mrs;
            e += u[64 + r] * mrs;
        }
        partv[g][s] = a;
        epartv[g][s] = e;
    }
    __syncthreads();
    if (warp == 0) {
        float t = qf[lane] * zs[lane] + qf[lane + 32] * zs[lane + 32];
#pragma unroll
        for (int o = 16; o; o >>= 1) t += __shfl_down_sync(FULL, t, o);
        if (lane == 0) sc[0] = t + 1e-6f;
    } else if (warp == 1) {
        float t = 0.0f;
#pragma unroll
        for (int k = 0; k < 4; ++k) t += rh[lane + k * 32] * r2w[lane + k * 32];
#pragma unroll
        for (int o = 16; o; o >>= 1) t += __shfl_down_sync(FULL, t, o);
        if (lane == 0) sc[1] = sigmoidf(t + r2b[0]);
    } else if (warp == 2 || warp == 3) {
        int s = (warp - 2) * 32 + lane;
        float a = 0.0f, e = 0.0f;
#pragma unroll
        for (int g = 0; g < 8; ++g) { a += partv[g][s]; e += epartv[g][s]; }
        linp[s] = a;
        errv[s] = e - u[128 + s];
    }
    __syncthreads();

    // ===== barrier 2 WAIT =====
    if (tid == 0) {
        volatile int* vc = &g_cntB[b];
        while (*vc < tgt2) { }
        __threadfence();
    }
    __syncthreads();

    // ===== score sum + decay, top-2 =====
    if (tid < 256) {
        int n = tid >> 2, p = tid & 3;
        float s = 0.0f;
#pragma unroll
        for (int h2 = p; h2 < H_N; h2 += 4)
            s += g_part[(b * H_N + h2) * NB + n];
        s += __shfl_down_sync(FULL, s, 2);
        s += __shfl_down_sync(FULL, s, 1);
        if (p == 0)
            sarr[n] = s * exp2f((float)(63 - n) * LOG2_GAMMA) * 0.0078125f;
    }
    __syncthreads();
    if (tid < 32) {
        float v0 = sarr[tid], v1 = sarr[tid + 32];
        float bv; int bi;
        if (v0 >= v1) { bv = v0; bi = tid; } else { bv = v1; bi = tid + 32; }
#pragma unroll
        for (int o = 16; o; o >>= 1) {
            float ov = __shfl_down_sync(FULL, bv, o);
            int   oi = __shfl_down_sync(FULL, bi, o);
            if (ov > bv || (ov == bv && oi < bi)) { bv = ov; bi = oi; }
        }
        int i1 = __shfl_sync(FULL, bi, 0);
        float w0 = (tid == i1)      ? -INFINITY : v0;
        float w1 = (tid + 32 == i1) ? -INFINITY : v1;
        float cv; int ci;
        if (w0 >= w1) { cv = w0; ci = tid; } else { cv = w1; ci = tid + 32; }
#pragma unroll
        for (int o = 16; o; o >>= 1) {
            float ov = __shfl_down_sync(FULL, cv, o);
            int   oi = __shfl_down_sync(FULL, ci, o);
            if (ov > cv || (ov == cv && oi < ci)) { cv = ov; ci = oi; }
        }
        if (tid == 0) { s_i1 = i1; s_i2 = ci; }
    }
    __syncthreads();

    // ===== compaction (smem bids -> widx) =====
    int nw;
    {
        int i1 = s_i1, i2 = s_i2, cur = curp[0];
        const int4* bs4 = (const int4*)bidsS;
        unsigned mbits = 0;
        int c = 0;
#pragma unroll
        for (int k = 0; k < 4; ++k) {
            int4 v = bs4[tid * 4 + k];
            if (v.x == i1 || v.x == i2 || v.x == cur) { mbits |= 1u << (k * 4 + 0); c++; }
            if (v.y == i1 || v.y == i2 || v.y == cur) { mbits |= 1u << (k * 4 + 1); c++; }
            if (v.z == i1 || v.z == i2 || v.z == cur) { mbits |= 1u << (k * 4 + 2); c++; }
            if (v.w == i1 || v.w == i2 || v.w == cur) { mbits |= 1u << (k * 4 + 3); c++; }
        }
        int inc = c;
#pragma unroll
        for (int o = 1; o < 32; o <<= 1) {
            int t = __shfl_up_sync(FULL, inc, o);
            if (lane >= o) inc += t;
        }
        if (lane == 31) warpCnt[warp] = inc;
        __syncthreads();
        if (tid == 0) {
            int t = 0;
#pragma unroll
            for (int k = 0; k < 16; ++k) { warpBase[k] = t; t += warpCnt[k]; }
            warpBase[16] = t;
        }
        __syncthreads();
        int off = warpBase[warp] + (inc - c);
        int base = tid * 16;
#pragma unroll
        for (int j = 0; j < 16; ++j)
            if ((mbits >> j) & 1u) widx[off++] = base + j;
        nw = warpBase[16];
    }
    __syncthreads();

    // ===== attention =====
    {
        const float4* qr = (const float4*)u;
        float lm = -INFINITY;
        for (int i = tid; i < nw; i += 512) {
            int w = widx[i];
            const float4* kr = (const float4*)&Kl[((size_t)bh * W_TOT + w) * 64];
            float d = 0.0f;
#pragma unroll
            for (int r4 = 0; r4 < 16; ++r4) {
                float4 kv = kr[r4], qv = qr[r4];
                d += kv.x * qv.x + kv.y * qv.y + kv.z * qv.z + kv.w * qv.w;
            }
            d *= 0.125f;
            logit[i] = d;
            lm = fmaxf(lm, d);
        }
#pragma unroll
        for (int o = 16; o; o >>= 1) lm = fmaxf(lm, __shfl_down_sync(FULL, lm, o));
        if (lane == 0) redw[warp] = lm;
        __syncthreads();
        if (warp == 0) {
            float m = (lane < 16) ? redw[lane] : -INFINITY;
#pragma unroll
            for (int o = 16; o; o >>= 1) m = fmaxf(m, __shfl_down_sync(FULL, m, o));
            if (lane == 0) s_max = m;
        }
        __syncthreads();

        float mx = s_max;
        float ls = 0.0f;
        for (int i = tid; i < nw; i += 512) {
            float e = expf(logit[i] - mx);
            logit[i] = e;
            ls += e;
        }
#pragma unroll
        for (int o = 16; o; o >>= 1) ls += __shfl_down_sync(FULL, ls, o);
        if (lane == 0) redw[warp] = ls;
        __syncthreads();
        if (warp == 0) {
            float m = (lane < 16) ? redw[lane] : 0.0f;
#pragma unroll
            for (int o = 16; o; o >>= 1) m += __shfl_down_sync(FULL, m, o);
            if (lane == 0) s_sum = m;
        }
        __syncthreads();

        int r4 = tid & 15, g = tid >> 4;
        float4 a4 = make_float4(0.0f, 0.0f, 0.0f, 0.0f);
        for (int i = g; i < nw; i += 32) {
            int w = widx[i];
            float pw = logit[i];
            float4 v = *(const float4*)&Vl[((size_t)bh * W_TOT + w) * 64 + r4 * 4];
            a4.x += pw * v.x; a4.y += pw * v.y; a4.z += pw * v.z; a4.w += pw * v.w;
        }
        *(float4*)&accv[g][r4 * 4] = a4;
        __syncthreads();
        if (tid < 64) {
            float a = 0.0f;
#pragma unroll
            for (int gg = 0; gg < 32; ++gg) a += accv[gg][tid];
            u[192 + tid] = a / s_sum;
        }
    }
    __syncthreads();

    // ===== gh fix-up: gh = gelu(gh_pre + g1w[:,192:256] @ attn) =====
    {
        int o = tid >> 1, half = tid & 1;
        const float4* wr = (const float4*)(g1w + (size_t)o * 256 + 192 + half * 32);
        const float4* uv4 = (const float4*)(u + 192) + half * 8;
        float a = 0.0f;
#pragma unroll
        for (int k = 0; k < 8; ++k) {
            float4 wv = wr[k], uv = uv4[k];
            a += wv.x * uv.x + wv.y * uv.y + wv.z * uv.z + wv.w * uv.w;
        }
        a += __shfl_down_sync(FULL, a, 1);
        if (half == 0) ghp[o] = geluf(ghp[o] + a);
    }
    __syncthreads();

    // ===== alpha/eta/theta via precomputed mean rows (3 dots of 256) =====
    if (warp < 3) {
        const float* mr = g_mrow + (b * 3 + warp) * 256;
        float t = 0.0f;
#pragma unroll
        for (int k = 0; k < 8; ++k) t += mr[lane + k * 32] * ghp[lane + k * 32];
#pragma unroll
        for (int o = 16; o; o >>= 1) t += __shfl_down_sync(FULL, t, o);
        if (lane == 0) {
            t += g_mb[b * 3 + warp];
            sc[2 + warp] = (warp == 0) ? sigmoidf(t) : softplusf(t);
        }
    }
    __syncthreads();

    // ===== out_lat, z_new =====
    if (tid < 64) {
        float l = linp[tid] / sc[0];
        float ps = sc[1];
        outlat[tid] = (1.0f - ps) * u[192 + tid] + ps * l;
        float zn = (1.0f - sc[2]) * zs[tid] + softplusf(u[64 + tid]);
        out[Z_OFF + bh * 64 + tid] = zn;
    }
    __syncthreads();

    // ===== state update + output projection =====
    {
        float eta = sc[3], theta = sc[4], oma = 1.0f - sc[2];
        float4* Mo4 = (float4*)(out + M_OFF + (size_t)bh * 4096);
        float4* So4 = (float4*)(out + S_OFF + (size_t)bh * 4096);
        const float4* ev4 = (const float4*)errv;
        const float4* Ms4 = (const float4*)Ms;
        const float4* Ss4 = (const float4*)Ss;
#pragma unroll
        for (int k = 0; k < 2; ++k) {
            int idx = tid + k * 512;
            int r = idx >> 4, s4 = idx & 15;
            float kl = u[64 + r];
            float4 e = ev4[s4];
            float4 sg = Ss4[idx];
            float4 ms = Ms4[idx];
            float4 sn;
            sn.x = eta * sg.x - theta * (kl * e.x);
            sn.y = eta * sg.y - theta * (kl * e.y);
            sn.z = eta * sg.z - theta * (kl * e.z);
            sn.w = eta * sg.w - theta * (kl * e.w);
            So4[idx] = sn;
            float4 mn;
            mn.x = oma * ms.x + sn.x;
            mn.y = oma * ms.y + sn.y;
            mn.z = oma * ms.z + sn.z;
            mn.w = oma * ms.w + sn.w;
            Mo4[idx] = mn;
        }
    }
    if (tid < 256) {
        int o = tid >> 1, half = tid & 1;
        const float4* er = (const float4*)(Ev + ((size_t)h * 128 + o) * 64) + half * 8;
        const float4* ov = (const float4*)outlat + half * 8;
        float a = 0.0f;
#pragma unroll
        for (int k = 0; k < 8; ++k) {
            float4 e = er[k], oo = ov[k];
            a += e.x * oo.x + e.y * oo.y + e.z * oo.z + e.w * oo.w;
        }
        a += __shfl_down_sync(FULL, a, 1);
        if (half == 0) out[OUT_OFF + b * 2048 + h * 128 + o] = a;
    }
}

// ============================================================
extern "C" void kernel_launch(void* const* d_in, const int* in_sizes, int n_in,
                              void* d_out, int out_size) {
    const float* x     = (const float*)d_in[0];
    const float* ln_g  = (const float*)d_in[1];
    const float* ln_b  = (const float*)d_in[2];
    const float* W_qkv = (const float*)d_in[3];
    const float* E_q   = (const float*)d_in[4];
    const float* E_k   = (const float*)d_in[5];
    const float* E_v   = (const float*)d_in[6];
    const float* K_lat = (const float*)d_in[7];
    const float* V_lat = (const float*)d_in[8];
    const float* bm    = (const float*)d_in[9];
    const float* M     = (const float*)d_in[10];
    const float* z     = (const float*)d_in[11];
    const float* S_prev= (const float*)d_in[12];
    const float* r1w   = (const float*)d_in[13];
    const float* r1b   = (const float*)d_in[14];
    const float* r2w   = (const float*)d_in[15];
    const float* r2b   = (const float*)d_in[16];
    const float* g1w   = (const float*)d_in[17];
    const float* g1b   = (const float*)d_in[18];
    const float* g2w   = (const float*)d_in[19];
    const float* g2b   = (const float*)d_in[20];
    const int*   bids  = (const int*)d_in[21];
    const int*   cur   = (const int*)d_in[22];
    float* out = (float*)d_out;

    static bool attr_done = false;
    if (!attr_done) {
        cudaFuncSetAttribute(k_all, cudaFuncAttributeMaxDynamicSharedMemorySize,
                             49152);
        attr_done = true;
    }

    k_all<<<B_SZ * H_N, 512, 49152>>>(x, ln_g, ln_b, W_qkv,
                                      K_lat, V_lat, bm, bids, cur,
                                      E_q, E_k, E_v, M, z, S_prev,
                                      r1w, r1b, r2w, r2b,
                                      g1w, g1b, g2w, g2b, out);
}

// round 10
// speedup vs baseline: 2.4241x; 1.0047x over previous
#include <cuda_runtime.h>
#include <cuda_bf16.h>
#include <cuda_pipeline.h>
#include <math.h>

#define B_SZ 8
#define D_MODEL 2048
#define H_N 16
#define R_DIM 64
#define W_TOT 8192
#define NB 64
#define QKV_COLS 6144

#define OUT_OFF 0
#define M_OFF   (B_SZ * H_N * 128)                       // 16384
#define Z_OFF   (M_OFF + B_SZ * H_N * R_DIM * R_DIM)     // 540672
#define S_OFF   (Z_OFF + B_SZ * H_N * R_DIM)             // 548864

#define LOG2_GAMMA (-0.043943347587597055f)
#define FULL 0xffffffffu

// -------- scratch (device globals; zero-init, monotone counters) --------
__device__ __align__(16) float g_qkv[B_SZ * QKV_COLS];
__device__ __align__(16) float g_part[B_SZ * H_N * NB];
__device__ __align__(16) float g_mrow[B_SZ * 3 * 256];
__device__ float g_mb[B_SZ * 3];
__device__ int g_grp[16];
__device__ int g_cntB[B_SZ];

__device__ __forceinline__ float softplusf(float x) {
    return fmaxf(x, 0.0f) + log1pf(expf(-fabsf(x)));
}
__device__ __forceinline__ float geluf(float x) {
    return 0.5f * x * (1.0f + erff(x * 0.70710678118654752440f));
}
__device__ __forceinline__ float sigmoidf(float x) {
    return 1.0f / (1.0f + expf(-x));
}

// ============================================================
// ONE kernel, grid=128 (b,h), block=512, dyn smem 48KB
// dyn: [0,16K) GEMM h-tile   [16K,48K) staged bids
// ============================================================
__global__ void __launch_bounds__(512) k_all(
    const float* __restrict__ x, const float* __restrict__ lg,
    const float* __restrict__ lb, const float* __restrict__ W,
    const float* __restrict__ Kl, const float* __restrict__ Vl,
    const float* __restrict__ bm, const int* __restrict__ bids,
    const int* __restrict__ curp,
    const float* __restrict__ Eq, const float* __restrict__ Ek,
    const float* __restrict__ Ev,
    const float* __restrict__ M, const float* __restrict__ z,
    const float* __restrict__ S_prev,
    const float* __restrict__ r1w, const float* __restrict__ r1b,
    const float* __restrict__ r2w, const float* __restrict__ r2b,
    const float* __restrict__ g1w, const float* __restrict__ g1b,
    const float* __restrict__ g2w, const float* __restrict__ g2b,
    float* __restrict__ out) {

    extern __shared__ __align__(16) char dyn[];
    float4* hs4  = (float4*)dyn;                 // [1024] GEMM phase only
    int*   bidsS = (int*)(dyn + 16384);          // [8192]

    __shared__ __align__(16) float Ms[4096];     // 16 KB
    __shared__ __align__(16) float Ss[4096];     // 16 KB
    __shared__ __align__(16) float bmS[4096];    // 16 KB
    __shared__ __align__(16) float u[256];       // [QL | KL | VL | attn]
    __shared__ __align__(16) float qkvS[384];
    __shared__ __align__(16) float projTmp[384];
    __shared__ __align__(16) float qf[64], zs[64], errv[64], linp[64], outlat[64];
    __shared__ __align__(16) float rh[128], ghp[256];
    __shared__ float partv[8][64];
    __shared__ float epartv[8][64];
    __shared__ float sarr[64];
    __shared__ __align__(16) float accv[32][64]; // 8 KB (also scratch for mean-rows)
    __shared__ float gm[32], gs[32], gw[32];
    __shared__ int widx[512];
    __shared__ int warpCnt[16];
    __shared__ int warpBase[17];
    __shared__ int s_i1, s_i2;
    __shared__ float s_sum;
    __shared__ float sc[8];   // 0:qz 1:p_skip 2:alpha 3:eta 4:theta
    __shared__ float smu[8], sinv[8];

    int bh = blockIdx.x;
    int b = bh >> 4, h = bh & 15;
    int tid = threadIdx.x;
    int warp = tid >> 5, lane = tid & 31;

    // ===== phase A: ASYNC stage M, S, bids, bm-slice, z (cp.async) =====
    {
        const float4* Mg4 = (const float4*)(M + (size_t)bh * 4096);
        const float4* Sg4 = (const float4*)(S_prev + (size_t)bh * 4096);
        float4* Ms4 = (float4*)Ms;
        float4* Ss4 = (float4*)Ss;
        float4* bmS4 = (float4*)bmS;
#pragma unroll
        for (int k = 0; k < 2; ++k) {
            int i = tid + k * 512;
            int n = i >> 4, c = i & 15;
            __pipeline_memcpy_async(&bmS4[i],
                ((const float4*)&bm[(((size_t)n * B_SZ + b) * H_N + h) * 64]) + c, 16);
        }
        const int4* br4 = (const int4*)(bids + b * W_TOT);
        int4* bs4 = (int4*)bidsS;
#pragma unroll
        for (int k = 0; k < 4; ++k)
            __pipeline_memcpy_async(&bs4[tid + k * 512], &br4[tid + k * 512], 16);
#pragma unroll
        for (int k = 0; k < 2; ++k)
            __pipeline_memcpy_async(&Ms4[tid + k * 512], &Mg4[tid + k * 512], 16);
#pragma unroll
        for (int k = 0; k < 2; ++k)
            __pipeline_memcpy_async(&Ss4[tid + k * 512], &Sg4[tid + k * 512], 16);
        if (tid < 16)
            __pipeline_memcpy_async(((float4*)zs) + tid,
                                    ((const float4*)(z + bh * 64)) + tid, 16);
        __pipeline_commit();
    }

    // ===== phase B: LN stats (warps 0-7) =====
    if (warp < 8) {
        int bb = warp;
        const float4* xr = (const float4*)(x + bb * D_MODEL);
        float s = 0.0f, ss = 0.0f;
#pragma unroll
        for (int i = 0; i < 16; ++i) {
            float4 v = xr[i * 32 + lane];
            s  += v.x + v.y + v.z + v.w;
            ss += v.x * v.x + v.y * v.y + v.z * v.z + v.w * v.w;
        }
#pragma unroll
        for (int o = 16; o; o >>= 1) {
            s  += __shfl_down_sync(FULL, s, o);
            ss += __shfl_down_sync(FULL, ss, o);
        }
        if (lane == 0) {
            float mu = s * (1.0f / D_MODEL);
            float var = ss * (1.0f / D_MODEL) - mu * mu;
            smu[bb] = mu;
            sinv[bb] = rsqrtf(var + 1e-5f);
        }
    }
    __syncthreads();

    // ===== phase C: QKV GEMM, cols [bh*48, bh*48+48), prefetched =====
    {
        int colBase = bh * 48 + warp * 3;
        float acc[3][8];
#pragma unroll
        for (int c = 0; c < 3; c++)
#pragma unroll
            for (int bb = 0; bb < 8; bb++) acc[c][bb] = 0.0f;

        for (int tile = 0; tile < 4; ++tile) {
            int k0 = tile * 512;
#pragma unroll
            for (int i2 = 0; i2 < 2; ++i2) {
                int i = tid + i2 * 512;
                int bb = i >> 7, kk = i & 127;
                float4 xv = *(const float4*)&x[bb * D_MODEL + k0 + kk * 4];
                float4 gv = *(const float4*)&lg[k0 + kk * 4];
                float4 bv = *(const float4*)&lb[k0 + kk * 4];
                float mu = smu[bb], inv = sinv[bb];
                float4 hv;
                hv.x = (xv.x - mu) * inv * gv.x + bv.x;
                hv.y = (xv.y - mu) * inv * gv.y + bv.y;
                hv.z = (xv.z - mu) * inv * gv.z + bv.z;
                hv.w = (xv.w - mu) * inv * gv.w + bv.w;
                hs4[bb * 128 + kk] = hv;
            }
            __syncthreads();

            const float* wp = W + (size_t)colBase * D_MODEL + k0 + lane * 4;
            float4 wcur[3], wnxt[3];
#pragma unroll
            for (int c = 0; c < 3; c++)
                wcur[c] = *(const float4*)(wp + (size_t)c * D_MODEL);
#pragma unroll
            for (int kk = 0; kk < 4; ++kk) {
                if (kk < 3) {
#pragma unroll
                    for (int c = 0; c < 3; c++)
                        wnxt[c] = *(const float4*)(wp + (size_t)c * D_MODEL + (kk + 1) * 128);
                }
                int k4 = lane + kk * 32;
#pragma unroll
                for (int bb = 0; bb < 8; bb++) {
                    float4 hv = hs4[bb * 128 + k4];
#pragma unroll
                    for (int c = 0; c < 3; c++)
                        acc[c][bb] += wcur[c].x * hv.x + wcur[c].y * hv.y
                                    + wcur[c].z * hv.z + wcur[c].w * hv.w;
                }
#pragma unroll
                for (int c = 0; c < 3; c++) wcur[c] = wnxt[c];
            }
            __syncthreads();
        }
#pragma unroll
        for (int c = 0; c < 3; c++)
#pragma unroll
            for (int bb = 0; bb < 8; bb++) {
                float v = acc[c][bb];
#pragma unroll
                for (int o = 16; o; o >>= 1) v += __shfl_down_sync(FULL, v, o);
                if (lane == 0) g_qkv[bb * QKV_COLS + colBase + c] = v;
            }
    }
    __threadfence();
    __syncthreads();

    // ===== barrier 1 (grouped on producer group h) =====
    if (tid == 0) {
        int t = atomicAdd(&g_grp[bh >> 3], 1);
        int tgt = ((t >> 3) + 1) * 8;
        volatile int* vc = &g_grp[h];
        while (*vc < tgt) { }
        __threadfence();
    }
    __syncthreads();

    // ===== phase D: stage qkv slice, coalesced projection =====
    if (tid < 384) qkvS[tid] = g_qkv[b * QKV_COLS + h * 384 + tid];
    __syncthreads();
    if (tid < 384) {
        int half = tid >= 192;
        int o = tid - half * 192;
        int which = o >> 6, r = o & 63;
        const float* E = (which == 0 ? Eq : (which == 1 ? Ek : Ev))
                         + (size_t)h * 8192 + half * 64 * 64 + r;
        const float* vec = qkvS + which * 128 + half * 64;
        float acc = 0.0f;
#pragma unroll 16
        for (int d = 0; d < 64; ++d) acc += vec[d] * E[d * 64];
        projTmp[tid] = acc;
    }
    __pipeline_wait_prior(0);   // staged smem (bm/bids/M/S/z) ready past here
    __syncthreads();
    if (tid < 192) u[tid] = projTmp[tid] + projTmp[tid + 192];
    __syncthreads();

    // ===== phase E: score partials from smem bm =====
    if (tid < 256) {
        int n = tid >> 2, q = tid & 3;
        const float4* mrow = (const float4*)(bmS + n * 64);
        const float4* qv4 = (const float4*)u;
        float p = 0.0f;
#pragma unroll
        for (int j = 0; j < 4; ++j) {
            float4 mv = mrow[q * 4 + j], qv = qv4[q * 4 + j];
            p += mv.x * qv.x + mv.y * qv.y + mv.z * qv.z + mv.w * qv.w;
        }
        p += __shfl_down_sync(FULL, p, 2);
        p += __shfl_down_sync(FULL, p, 1);
        if (q == 0) g_part[(b * H_N + h) * NB + n] = p;
    }
    __threadfence();
    __syncthreads();

    // ===== mean-rows of g2w (blocks h<3 only) =====
    if (h < 3) {
        float* tmp = (float*)accv;
        int c = tid & 255, halfr = tid >> 8;
        const float* g2 = g2w + (size_t)(h * 64 + halfr * 32) * 256 + c;
        float s = 0.0f;
#pragma unroll
        for (int r = 0; r < 32; ++r) s += g2[r * 256];
        tmp[halfr * 256 + c] = s;
        __syncthreads();
        if (tid < 256)
            g_mrow[(b * 3 + h) * 256 + tid] = (tmp[tid] + tmp[256 + tid]) * (1.0f / 64.0f);
        if (tid == 256) {
            float t = 0.0f;
#pragma unroll
            for (int k = 0; k < 64; ++k) t += g2b[h * 64 + k];
            g_mb[b * 3 + h] = t * (1.0f / 64.0f);
        }
        __threadfence();
        __syncthreads();
    }

    // ===== barrier 2 ARRIVE =====
    int tgt2 = 0;
    if (tid == 0) {
        int t = atomicAdd(&g_cntB[b], 1);
        tgt2 = t - (t & 15) + 16;
    }

    // ===== pre-attention work while peers arrive =====
    {
        int o = tid >> 1, half = tid & 1;
        const float4* wr = (const float4*)(g1w + (size_t)o * 256 + half * 96);
        const float4* uv4 = (const float4*)u + half * 24;
        float a = 0.0f;
#pragma unroll
        for (int k = 0; k < 24; ++k) {
            float4 wv = wr[k], uv = uv4[k];
            a += wv.x * uv.x + wv.y * uv.y + wv.z * uv.z + wv.w * uv.w;
        }
        a += __shfl_down_sync(FULL, a, 1);
        if (half == 0) ghp[o] = a + g1b[o];
    }
    if (tid < 64) qf[tid] = softplusf(u[tid]);
    if (tid >= 256 && tid < 384) {
        int o = tid - 256;
        const float4* wr = (const float4*)(r1w + o * 64);
        const float4* qv = (const float4*)u;
        float a = r1b[o];
#pragma unroll
        for (int k = 0; k < 16; ++k) {
            float4 wv = wr[k], uv = qv[k];
            a += wv.x * uv.x + wv.y * uv.y + wv.z * uv.z + wv.w * uv.w;
        }
        rh[o] = geluf(a);
    }
    __syncthreads();
    {
        int s = tid & 63, g = tid >> 6;
        float a = 0.0f, e = 0.0f;
        for (int r = g; r < 64; r += 8) {
            float mrs = Ms[r * 64 + s];
            a += qf[r] * mrs;
            e += u[64 + r] * mrs;
        }
        partv[g][s] = a;
        epartv[g][s] = e;
    }
    __syncthreads();
    if (warp == 0) {
        float t = qf[lane] * zs[lane] + qf[lane + 32] * zs[lane + 32];
#pragma unroll
        for (int o = 16; o; o >>= 1) t += __shfl_down_sync(FULL, t, o);
        if (lane == 0) sc[0] = t + 1e-6f;
    } else if (warp == 1) {
        float t = 0.0f;
#pragma unroll
        for (int k = 0; k < 4; ++k) t += rh[lane + k * 32] * r2w[lane + k * 32];
#pragma unroll
        for (int o = 16; o; o >>= 1) t += __shfl_down_sync(FULL, t, o);
        if (lane == 0) sc[1] = sigmoidf(t + r2b[0]);
    } else if (warp == 2 || warp == 3) {
        int s = (warp - 2) * 32 + lane;
        float a = 0.0f, e = 0.0f;
#pragma unroll
        for (int g = 0; g < 8; ++g) { a += partv[g][s]; e += epartv[g][s]; }
        linp[s] = a;
        errv[s] = e - u[128 + s];
    }
    __syncthreads();

    // ===== barrier 2 WAIT =====
    if (tid == 0) {
        volatile int* vc = &g_cntB[b];
        while (*vc < tgt2) { }
        __threadfence();
    }
    __syncthreads();

    // ===== score sum + decay, top-2 =====
    if (tid < 256) {
        int n = tid >> 2, p = tid & 3;
        float s = 0.0f;
#pragma unroll
        for (int h2 = p; h2 < H_N; h2 += 4)
            s += g_part[(b * H_N + h2) * NB + n];
        s += __shfl_down_sync(FULL, s, 2);
        s += __shfl_down_sync(FULL, s, 1);
        if (p == 0)
            sarr[n] = s * exp2f((float)(63 - n) * LOG2_GAMMA) * 0.0078125f;
    }
    __syncthreads();
    if (tid < 32) {
        float v0 = sarr[tid], v1 = sarr[tid + 32];
        float bv; int bi;
        if (v0 >= v1) { bv = v0; bi = tid; } else { bv = v1; bi = tid + 32; }
#pragma unroll
        for (int o = 16; o; o >>= 1) {
            float ov = __shfl_down_sync(FULL, bv, o);
            int   oi = __shfl_down_sync(FULL, bi, o);
            if (ov > bv || (ov == bv && oi < bi)) { bv = ov; bi = oi; }
        }
        int i1 = __shfl_sync(FULL, bi, 0);
        float w0 = (tid == i1)      ? -INFINITY : v0;
        float w1 = (tid + 32 == i1) ? -INFINITY : v1;
        float cv; int ci;
        if (w0 >= w1) { cv = w0; ci = tid; } else { cv = w1; ci = tid + 32; }
#pragma unroll
        for (int o = 16; o; o >>= 1) {
            float ov = __shfl_down_sync(FULL, cv, o);
            int   oi = __shfl_down_sync(FULL, ci, o);
            if (ov > cv || (ov == cv && oi < ci)) { cv = ov; ci = oi; }
        }
        if (tid == 0) { s_i1 = i1; s_i2 = ci; }
    }
    __syncthreads();

    // ===== compaction (smem bids -> widx) =====
    int nw;
    {
        int i1 = s_i1, i2 = s_i2, cur = curp[0];
        const int4* bs4 = (const int4*)bidsS;
        unsigned mbits = 0;
        int c = 0;
#pragma unroll
        for (int k = 0; k < 4; ++k) {
            int4 v = bs4[tid * 4 + k];
            if (v.x == i1 || v.x == i2 || v.x == cur) { mbits |= 1u << (k * 4 + 0); c++; }
            if (v.y == i1 || v.y == i2 || v.y == cur) { mbits |= 1u << (k * 4 + 1); c++; }
            if (v.z == i1 || v.z == i2 || v.z == cur) { mbits |= 1u << (k * 4 + 2); c++; }
            if (v.w == i1 || v.w == i2 || v.w == cur) { mbits |= 1u << (k * 4 + 3); c++; }
        }
        int inc = c;
#pragma unroll
        for (int o = 1; o < 32; o <<= 1) {
            int t = __shfl_up_sync(FULL, inc, o);
            if (lane >= o) inc += t;
        }
        if (lane == 31) warpCnt[warp] = inc;
        __syncthreads();
        if (tid == 0) {
            int t = 0;
#pragma unroll
            for (int k = 0; k < 16; ++k) { warpBase[k] = t; t += warpCnt[k]; }
            warpBase[16] = t;
        }
        __syncthreads();
        int off = warpBase[warp] + (inc - c);
        int base = tid * 16;
#pragma unroll
        for (int j = 0; j < 16; ++j)
            if ((mbits >> j) & 1u) widx[off++] = base + j;
        nw = warpBase[16];
    }
    __syncthreads();

    // ===== attention: single-pass online softmax (K+V loaded together) =====
    {
        int grp = tid >> 4, r4 = tid & 15;
        float4 qv = ((const float4*)u)[r4];
        float m = -INFINITY, s = 0.0f;
        float4 acc = make_float4(0.0f, 0.0f, 0.0f, 0.0f);
        for (int i = grp; i < nw; i += 32) {
            int w = widx[i];
            size_t rowo = ((size_t)bh * W_TOT + w) * 64 + r4 * 4;
            float4 kv = *(const float4*)&Kl[rowo];
            float4 vv = *(const float4*)&Vl[rowo];
            float d = kv.x * qv.x + kv.y * qv.y + kv.z * qv.z + kv.w * qv.w;
            d += __shfl_xor_sync(FULL, d, 1);
            d += __shfl_xor_sync(FULL, d, 2);
            d += __shfl_xor_sync(FULL, d, 4);
            d += __shfl_xor_sync(FULL, d, 8);
            d *= 0.125f;                     // 1/sqrt(64)
            float mn = fmaxf(m, d);
            float rs = expf(m - mn);         // 0 on first iteration
            float p  = expf(d - mn);
            s = s * rs + p;
            acc.x = acc.x * rs + p * vv.x;
            acc.y = acc.y * rs + p * vv.y;
            acc.z = acc.z * rs + p * vv.z;
            acc.w = acc.w * rs + p * vv.w;
            m = mn;
        }
        *(float4*)&accv[grp][r4 * 4] = acc;
        if (r4 == 0) { gm[grp] = m; gs[grp] = s; }
        __syncthreads();
        if (warp == 0) {
            float mv = gm[lane];
            float mm = mv;
#pragma unroll
            for (int o = 16; o; o >>= 1) mm = fmaxf(mm, __shfl_xor_sync(FULL, mm, o));
            float wgt = (mv == -INFINITY) ? 0.0f : expf(mv - mm);
            gw[lane] = wgt;
            float dn = gs[lane] * wgt;
#pragma unroll
            for (int o = 16; o; o >>= 1) dn += __shfl_xor_sync(FULL, dn, o);
            if (lane == 0) s_sum = dn;
        }
        __syncthreads();
        if (tid < 64) {
            float a = 0.0f;
#pragma unroll
            for (int g = 0; g < 32; ++g) a += accv[g][tid] * gw[g];
            u[192 + tid] = a / s_sum;
        }
    }
    __syncthreads();

    // ===== gh fix-up: gh = gelu(gh_pre + g1w[:,192:256] @ attn) =====
    {
        int o = tid >> 1, half = tid & 1;
        const float4* wr = (const float4*)(g1w + (size_t)o * 256 + 192 + half * 32);
        const float4* uv4 = (const float4*)(u + 192) + half * 8;
        float a = 0.0f;
#pragma unroll
        for (int k = 0; k < 8; ++k) {
            float4 wv = wr[k], uv = uv4[k];
            a += wv.x * uv.x + wv.y * uv.y + wv.z * uv.z + wv.w * uv.w;
        }
        a += __shfl_down_sync(FULL, a, 1);
        if (half == 0) ghp[o] = geluf(ghp[o] + a);
    }
    __syncthreads();

    // ===== alpha/eta/theta via precomputed mean rows =====
    if (warp < 3) {
        const float* mr = g_mrow + (b * 3 + warp) * 256;
        float t = 0.0f;
#pragma unroll
        for (int k = 0; k < 8; ++k) t += mr[lane + k * 32] * ghp[lane + k * 32];
#pragma unroll
        for (int o = 16; o; o >>= 1) t += __shfl_down_sync(FULL, t, o);
        if (lane == 0) {
            t += g_mb[b * 3 + warp];
            sc[2 + warp] = (warp == 0) ? sigmoidf(t) : softplusf(t);
        }
    }
    __syncthreads();

    // ===== out_lat, z_new =====
    if (tid < 64) {
        float l = linp[tid] / sc[0];
        float ps = sc[1];
        outlat[tid] = (1.0f - ps) * u[192 + tid] + ps * l;
        float zn = (1.0f - sc[2]) * zs[tid] + softplusf(u[64 + tid]);
        out[Z_OFF + bh * 64 + tid] = zn;
    }
    __syncthreads();

    // ===== state update + output projection =====
    {
        float eta = sc[3], theta = sc[4], oma = 1.0f - sc[2];
        float4* Mo4 = (float4*)(out + M_OFF + (size_t)bh * 4096);
        float4* So4 = (float4*)(out + S_OFF + (size_t)bh * 4096);
        const float4* ev4 = (const float4*)errv;
        const float4* Ms4 = (const float4*)Ms;
        const float4* Ss4 = (const float4*)Ss;
#pragma unroll
        for (int k = 0; k < 2; ++k) {
            int idx = tid + k * 512;
            int r = idx >> 4, s4 = idx & 15;
            float kl = u[64 + r];
            float4 e = ev4[s4];
            float4 sg = Ss4[idx];
            float4 ms = Ms4[idx];
            float4 sn;
            sn.x = eta * sg.x - theta * (kl * e.x);
            sn.y = eta * sg.y - theta * (kl * e.y);
            sn.z = eta * sg.z - theta * (kl * e.z);
            sn.w = eta * sg.w - theta * (kl * e.w);
            So4[idx] = sn;
            float4 mn;
            mn.x = oma * ms.x + sn.x;
            mn.y = oma * ms.y + sn.y;
            mn.z = oma * ms.z + sn.z;
            mn.w = oma * ms.w + sn.w;
            Mo4[idx] = mn;
        }
    }
    if (tid < 256) {
        int o = tid >> 1, half = tid & 1;
        const float4* er = (const float4*)(Ev + ((size_t)h * 128 + o) * 64) + half * 8;
        const float4* ov = (const float4*)outlat + half * 8;
        float a = 0.0f;
#pragma unroll
        for (int k = 0; k < 8; ++k) {
            float4 e = er[k], oo = ov[k];
            a += e.x * oo.x + e.y * oo.y + e.z * oo.z + e.w * oo.w;
        }
        a += __shfl_down_sync(FULL, a, 1);
        if (half == 0) out[OUT_OFF + b * 2048 + h * 128 + o] = a;
    }
}

// ============================================================
extern "C" void kernel_launch(void* const* d_in, const int* in_sizes, int n_in,
                              void* d_out, int out_size) {
    const float* x     = (const float*)d_in[0];
    const float* ln_g  = (const float*)d_in[1];
    const float* ln_b  = (const float*)d_in[2];
    const float* W_qkv = (const float*)d_in[3];
    const float* E_q   = (const float*)d_in[4];
    const float* E_k   = (const float*)d_in[5];
    const float* E_v   = (const float*)d_in[6];
    const float* K_lat = (const float*)d_in[7];
    const float* V_lat = (const float*)d_in[8];
    const float* bm    = (const float*)d_in[9];
    const float* M     = (const float*)d_in[10];
    const float* z     = (const float*)d_in[11];
    const float* S_prev= (const float*)d_in[12];
    const float* r1w   = (const float*)d_in[13];
    const float* r1b   = (const float*)d_in[14];
    const float* r2w   = (const float*)d_in[15];
    const float* r2b   = (const float*)d_in[16];
    const float* g1w   = (const float*)d_in[17];
    const float* g1b   = (const float*)d_in[18];
    const float* g2w   = (const float*)d_in[19];
    const float* g2b   = (const float*)d_in[20];
    const int*   bids  = (const int*)d_in[21];
    const int*   cur   = (const int*)d_in[22];
    float* out = (float*)d_out;

    static bool attr_done = false;
    if (!attr_done) {
        cudaFuncSetAttribute(k_all, cudaFuncAttributeMaxDynamicSharedMemorySize,
                             49152);
        attr_done = true;
    }

    k_all<<<B_SZ * H_N, 512, 49152>>>(x, ln_g, ln_b, W_qkv,
                                      K_lat, V_lat, bm, bids, cur,
                                      E_q, E_k, E_v, M, z, S_prev,
                                      r1w, r1b, r2w, r2b,
                                      g1w, g1b, g2w, g2b, out);
}